// round 8
// baseline (speedup 1.0000x reference)
#include <cuda_runtime.h>
#include <cstdint>

// Problem constants
#define BATCH 2
#define SEQ   2048
#define DIM   1024
#define NH    16
#define HD    64
#define MROWS (BATCH * SEQ)   // 4096

// Scratch (allocation-free rule: __device__ globals)
__device__ float g_Q[BATCH * NH * SEQ * HD];   // [b,h,s,hd] (tf32-rounded)
__device__ float g_K[BATCH * NH * SEQ * HD];   // (tf32-rounded)
__device__ float g_V[BATCH * NH * SEQ * HD];   // (tf32-rounded)
__device__ float g_A[BATCH * SEQ * DIM];       // attn out [b,s,h*hd] (tf32-rounded)
__device__ float g_Wc[4 * DIM * DIM];          // tf32-rounded (Wq,Wk,Wv k-permuted; Wo plain)
__device__ float g_Xc[3 * MROWS * DIM];        // tf32-rounded, k-permuted q,k,v

// ---------------------------------------------------------------------------
// Helpers
// ---------------------------------------------------------------------------
__device__ __forceinline__ uint32_t smem_u32(const void* p) {
    uint32_t a;
    asm("{ .reg .u64 t; cvta.to.shared.u64 t, %1; cvt.u32.u64 %0, t; }" : "=r"(a) : "l"(p));
    return a;
}

#define CP_ASYNC16(dst, src) \
    asm volatile("cp.async.cg.shared.global [%0], [%1], 16;" :: "r"(dst), "l"(src))
#define CP_ASYNC4(dst, src) \
    asm volatile("cp.async.ca.shared.global [%0], [%1], 4;" :: "r"(dst), "l"(src))
#define CP_ASYNC_COMMIT() asm volatile("cp.async.commit_group;" ::: "memory")
#define CP_ASYNC_WAIT(n)  asm volatile("cp.async.wait_group %0;" :: "n"(n) : "memory")

__device__ __forceinline__ uint32_t f2tf32(float x) {
    uint32_t r;
    asm("cvt.rna.tf32.f32 %0, %1;" : "=r"(r) : "f"(x));
    return r;
}

#define MMA_TF32(d, av, bv)                                                   \
    asm volatile("mma.sync.aligned.m16n8k8.row.col.f32.tf32.tf32.f32 "        \
                 "{%0,%1,%2,%3}, {%4,%5,%6,%7}, {%8,%9}, {%0,%1,%2,%3};"      \
                 : "+f"((d)[0]), "+f"((d)[1]), "+f"((d)[2]), "+f"((d)[3])     \
                 : "r"((av)[0]), "r"((av)[1]), "r"((av)[2]), "r"((av)[3]),    \
                   "r"((bv)[0]), "r"((bv)[1]))

// Fast exp2 on the FMA pipe. Rel err ~3e-6.
__device__ __forceinline__ float fast_exp2(float x) {
    x = fmaxf(x, -126.0f);
    float t = x + 12582912.0f;            // 2^23 + 2^22
    float i = t - 12582912.0f;
    float f = x - i;
    float p = 1.3333558e-3f;
    p = fmaf(p, f, 9.6181291e-3f);
    p = fmaf(p, f, 5.5504109e-2f);
    p = fmaf(p, f, 2.4022651e-1f);
    p = fmaf(p, f, 6.9314718e-1f);
    p = fmaf(p, f, 1.0f);
    int ib = __float_as_int(t) << 23;     // == i << 23 exactly
    return __int_as_float(__float_as_int(p) + ib);
}

// ---------------------------------------------------------------------------
// Fused tf32 rounding pre-pass; segments may also permute each 8-float
// k-group to [k0,k4,k1,k5,k2,k6,k3,k7] so (k, k+4) mma pairs become adjacent.
// grid = (1024, 7); blockIdx.y selects segment. 2 float4-pairs per thread.
// ---------------------------------------------------------------------------
struct ConvArgs {
    const float* src[7];
    float* dst[7];
    int npair[7];   // number of 8-float pairs
    int perm[7];    // 1 = k-permute, 0 = identity
};

__global__ __launch_bounds__(256) void conv_tf32_all(ConvArgs a) {
    const int seg = blockIdx.y;
    const float* src = a.src[seg];
    float* dst = a.dst[seg];
    const int np = a.npair[seg];
    const int perm = a.perm[seg];
    int p0 = blockIdx.x * 512 + threadIdx.x;
    if (p0 >= np) return;
#pragma unroll
    for (int t = 0; t < 2; t++) {
        int pr = p0 + t * 256;
        if (pr < np) {
            float4 v0 = ((const float4*)src)[2 * pr];
            float4 v1 = ((const float4*)src)[2 * pr + 1];
            v0.x = __uint_as_float(f2tf32(v0.x));
            v0.y = __uint_as_float(f2tf32(v0.y));
            v0.z = __uint_as_float(f2tf32(v0.z));
            v0.w = __uint_as_float(f2tf32(v0.w));
            v1.x = __uint_as_float(f2tf32(v1.x));
            v1.y = __uint_as_float(f2tf32(v1.y));
            v1.z = __uint_as_float(f2tf32(v1.z));
            v1.w = __uint_as_float(f2tf32(v1.w));
            float4 d0, d1;
            if (perm) {
                d0.x = v0.x; d0.y = v1.x; d0.z = v0.y; d0.w = v1.y;
                d1.x = v0.z; d1.y = v1.z; d1.z = v0.w; d1.w = v1.w;
            } else {
                d0 = v0; d1 = v1;
            }
            ((float4*)dst)[2 * pr] = d0;
            ((float4*)dst)[2 * pr + 1] = d1;
        }
    }
}

// ---------------------------------------------------------------------------
// GEMM common geometry
// ---------------------------------------------------------------------------
#define GBM 128
#define GBN 256
#define GBK 32
#define NKT (DIM / GBK)                 // 32
#define SA_BYTES (GBM * GBK * 4)        // 16384
#define SB_BYTES (GBN * GBK * 4)        // 32768
#define SM_GEMM_TOTAL (2 * (SA_BYTES + SB_BYTES))   // 98304

struct GemmArgs {
    const float* A;
    const float* W;
    const float* bias;
    float* C;
};

// LDS.64 helper for k-permuted + XOR-swizzled smem (32-float rows).
__device__ __forceinline__ float2 lds2_sw(const float* base, int row, int f) {
    int phys = row * 32 + ((((f >> 2) ^ (row & 7))) << 2) + (f & 3);
    return *(const float2*)&base[phys];
}

// ---------------------------------------------------------------------------
// QKV GEMM: 256 threads, 8 warps (2m x 4n), warp tile 64x64. k-PERMUTED
// operands -> all fragment loads are LDS.64. Writes split-head Q/K/V.
// ---------------------------------------------------------------------------
__global__ __launch_bounds__(256, 1) void gemm_qkv(GemmArgs a0, GemmArgs a1, GemmArgs a2) {
    const GemmArgs& ar = (blockIdx.z == 0) ? a0 : (blockIdx.z == 1) ? a1 : a2;
    const float* __restrict__ A = ar.A;
    const float* __restrict__ W = ar.W;
    const float* __restrict__ bias = ar.bias;
    float* __restrict__ C = ar.C;

    extern __shared__ char smem[];
    const float* sAf = (const float*)smem;               // [2][128][32]
    const float* sBf = (const float*)(smem + 2 * SA_BYTES);
    const uint32_t sA = smem_u32(smem);
    const uint32_t sB = sA + 2 * SA_BYTES;

    const int tid = threadIdx.x;
    const int lane = tid & 31;
    const int wid = tid >> 5;
    const int wm = wid & 1;
    const int wn = wid >> 1;
    const int g = lane >> 2;
    const int tig = lane & 3;
    const int m0 = blockIdx.y * GBM;
    const int n0 = blockIdx.x * GBN;

    float acc[4][8][4];
#pragma unroll
    for (int i = 0; i < 4; i++)
#pragma unroll
        for (int j = 0; j < 8; j++)
#pragma unroll
            for (int c = 0; c < 4; c++) acc[i][j][c] = 0.f;

    auto stage = [&](int kt, int buf) {
        const int k0 = kt * GBK;
#pragma unroll
        for (int t = 0; t < 4; t++) {
            int idx = tid + t * 256;
            int row = idx >> 3;
            int c = idx & 7;
            uint32_t dst = sA + buf * SA_BYTES + row * 128 + ((c ^ (row & 7)) << 4);
            CP_ASYNC16(dst, &A[(size_t)(m0 + row) * DIM + k0 + c * 4]);
        }
#pragma unroll
        for (int t = 0; t < 8; t++) {
            int idx = tid + t * 256;
            int row = idx >> 3;
            int c = idx & 7;
            uint32_t dst = sB + buf * SB_BYTES + row * 128 + ((c ^ (row & 7)) << 4);
            CP_ASYNC16(dst, &W[(size_t)(n0 + row) * DIM + k0 + c * 4]);
        }
    };

    stage(0, 0);
    CP_ASYNC_COMMIT();

    for (int kt = 0; kt < NKT; kt++) {
        if (kt + 1 < NKT) {
            stage(kt + 1, (kt + 1) & 1);
            CP_ASYNC_COMMIT();
            CP_ASYNC_WAIT(1);
        } else {
            CP_ASYNC_WAIT(0);
        }
        __syncthreads();

        const float* Ab = sAf + (kt & 1) * (SA_BYTES / 4);
        const float* Bb = sBf + (kt & 1) * (SB_BYTES / 4);
#pragma unroll
        for (int s = 0; s < 4; s++) {
            const int f = 8 * s + 2 * tig;   // permuted pos of (k1, k2) pair
            uint32_t a[4][4];
#pragma unroll
            for (int i = 0; i < 4; i++) {
                int r1 = wm * 64 + i * 16 + g;
                int r2 = r1 + 8;
                float2 p1 = lds2_sw(Ab, r1, f);   // (a0, a2)
                float2 p2 = lds2_sw(Ab, r2, f);   // (a1, a3)
                a[i][0] = __float_as_uint(p1.x);
                a[i][1] = __float_as_uint(p2.x);
                a[i][2] = __float_as_uint(p1.y);
                a[i][3] = __float_as_uint(p2.y);
            }
            uint32_t bf[8][2];
#pragma unroll
            for (int j = 0; j < 8; j++) {
                int rn = wn * 64 + j * 8 + g;
                float2 pb = lds2_sw(Bb, rn, f);   // (b0, b1)
                bf[j][0] = __float_as_uint(pb.x);
                bf[j][1] = __float_as_uint(pb.y);
            }
#pragma unroll
            for (int i = 0; i < 4; i++)
#pragma unroll
                for (int j = 0; j < 8; j++) MMA_TF32(acc[i][j], a[i], bf[j]);
        }
        __syncthreads();
    }

#pragma unroll
    for (int i = 0; i < 4; i++) {
        const int m1 = m0 + wm * 64 + i * 16 + g;
        const int m2 = m1 + 8;
#pragma unroll
        for (int j = 0; j < 8; j++) {
            const int n = n0 + wn * 64 + j * 8 + tig * 2;
            const float2 bb = *(const float2*)&bias[n];
            float2 r1, r2;
            r1.x = __uint_as_float(f2tf32(acc[i][j][0] + bb.x));
            r1.y = __uint_as_float(f2tf32(acc[i][j][1] + bb.y));
            r2.x = __uint_as_float(f2tf32(acc[i][j][2] + bb.x));
            r2.y = __uint_as_float(f2tf32(acc[i][j][3] + bb.y));
            int h = n >> 6;
            int hd = n & (HD - 1);
            {
                int b = m1 >> 11, sq = m1 & (SEQ - 1);
                *(float2*)&C[((size_t)((b * NH + h) * SEQ + sq)) * HD + hd] = r1;
            }
            {
                int b = m2 >> 11, sq = m2 & (SEQ - 1);
                *(float2*)&C[((size_t)((b * NH + h) * SEQ + sq)) * HD + hd] = r2;
            }
        }
    }
}

// ---------------------------------------------------------------------------
// Output GEMM: 512 threads, 16 warps (4m x 4n), warp tile 32x64.
// Plain (unpermuted) operands, scalar fragment loads. (R7 config, measured.)
// ---------------------------------------------------------------------------
__global__ __launch_bounds__(512, 1) void gemm_out(const float* __restrict__ A,
                                                   const float* __restrict__ W,
                                                   const float* __restrict__ bias,
                                                   float* __restrict__ C) {
    extern __shared__ char smem[];
    const float* sAf = (const float*)smem;
    const float* sBf = (const float*)(smem + 2 * SA_BYTES);
    const uint32_t sA = smem_u32(smem);
    const uint32_t sB = sA + 2 * SA_BYTES;

    const int tid = threadIdx.x;
    const int lane = tid & 31;
    const int wid = tid >> 5;
    const int wm = wid & 3;
    const int wn = wid >> 2;
    const int g = lane >> 2;
    const int tig = lane & 3;
    const int m0 = blockIdx.y * GBM;
    const int n0 = blockIdx.x * GBN;

    float acc[2][8][4];
#pragma unroll
    for (int i = 0; i < 2; i++)
#pragma unroll
        for (int j = 0; j < 8; j++)
#pragma unroll
            for (int c = 0; c < 4; c++) acc[i][j][c] = 0.f;

    auto stage = [&](int kt, int buf) {
        const int k0 = kt * GBK;
#pragma unroll
        for (int t = 0; t < 2; t++) {
            int idx = tid + t * 512;
            int row = idx >> 3;
            int c = idx & 7;
            uint32_t dst = sA + buf * SA_BYTES + row * 128 + ((c ^ (row & 7)) << 4);
            CP_ASYNC16(dst, &A[(size_t)(m0 + row) * DIM + k0 + c * 4]);
        }
#pragma unroll
        for (int t = 0; t < 4; t++) {
            int idx = tid + t * 512;
            int row = idx >> 3;
            int c = idx & 7;
            uint32_t dst = sB + buf * SB_BYTES + row * 128 + ((c ^ (row & 7)) << 4);
            CP_ASYNC16(dst, &W[(size_t)(n0 + row) * DIM + k0 + c * 4]);
        }
    };

    stage(0, 0);
    CP_ASYNC_COMMIT();

    for (int kt = 0; kt < NKT; kt++) {
        if (kt + 1 < NKT) {
            stage(kt + 1, (kt + 1) & 1);
            CP_ASYNC_COMMIT();
            CP_ASYNC_WAIT(1);
        } else {
            CP_ASYNC_WAIT(0);
        }
        __syncthreads();

        const float* Ab = sAf + (kt & 1) * (SA_BYTES / 4);
        const float* Bb = sBf + (kt & 1) * (SB_BYTES / 4);
#pragma unroll
        for (int s = 0; s < 4; s++) {
            const int k1 = s * 8 + tig;
            const int k2 = k1 + 4;
            uint32_t a[2][4];
#pragma unroll
            for (int i = 0; i < 2; i++) {
                int r1 = wm * 32 + i * 16 + g;
                int r2 = r1 + 8;
                a[i][0] = __float_as_uint(Ab[r1 * 32 + (k1 ^ ((r1 & 7) << 2))]);
                a[i][1] = __float_as_uint(Ab[r2 * 32 + (k1 ^ ((r2 & 7) << 2))]);
                a[i][2] = __float_as_uint(Ab[r1 * 32 + (k2 ^ ((r1 & 7) << 2))]);
                a[i][3] = __float_as_uint(Ab[r2 * 32 + (k2 ^ ((r2 & 7) << 2))]);
            }
            uint32_t bf[8][2];
#pragma unroll
            for (int j = 0; j < 8; j++) {
                int rn = wn * 64 + j * 8 + g;
                bf[j][0] = __float_as_uint(Bb[rn * 32 + (k1 ^ ((rn & 7) << 2))]);
                bf[j][1] = __float_as_uint(Bb[rn * 32 + (k2 ^ ((rn & 7) << 2))]);
            }
#pragma unroll
            for (int i = 0; i < 2; i++)
#pragma unroll
                for (int j = 0; j < 8; j++) MMA_TF32(acc[i][j], a[i], bf[j]);
        }
        __syncthreads();
    }

#pragma unroll
    for (int i = 0; i < 2; i++) {
        const int m1 = m0 + wm * 32 + i * 16 + g;
        const int m2 = m1 + 8;
#pragma unroll
        for (int j = 0; j < 8; j++) {
            const int n = n0 + wn * 64 + j * 8 + tig * 2;
            const float2 bb = *(const float2*)&bias[n];
            float2 r1, r2;
            r1.x = acc[i][j][0] + bb.x;
            r1.y = acc[i][j][1] + bb.y;
            r2.x = acc[i][j][2] + bb.x;
            r2.y = acc[i][j][3] + bb.y;
            *(float2*)&C[(size_t)m1 * DIM + n] = r1;
            *(float2*)&C[(size_t)m2 * DIM + n] = r2;
        }
    }
}

// ---------------------------------------------------------------------------
// Tensor-core flash attention (tf32 mma.sync), M=32 rows per warp. Unchanged.
// ---------------------------------------------------------------------------
#define FKT 64
#define KVS 72          // smem row stride (floats)
#define FNT (SEQ / FKT) // 32

#define F_KSM 0
#define F_VSM (2 * FKT * KVS)                 // 9216
#define F_PSM (F_VSM + 2 * FKT * KVS)         // 18432
#define F_MSK (F_PSM + 128 * KVS)             // 27648 (int region)
#define F_TOTAL_FLOATS (F_MSK + 2 * FKT)      // 27776
#define FLASH_SMEM_BYTES (F_TOTAL_FLOATS * 4) // 111104

#define CS 0.18033688f  // 0.125 * log2(e)

__global__ __launch_bounds__(128) void flash_attn_tc(const int* __restrict__ mask,
                                                     float* __restrict__ Out) {
    extern __shared__ char smem[];
    float* smf = (float*)smem;
    int* smi = (int*)smem;
    const uint32_t sbase = smem_u32(smem);

    const int b = blockIdx.z;
    const int h = blockIdx.y;
    const int tid = threadIdx.x;
    const int w = tid >> 5;
    const int lane = tid & 31;
    const int g = lane >> 2;
    const int tig = lane & 3;
    const int qr0 = blockIdx.x * 128 + w * 32;

    const float* Qp = g_Q + ((size_t)((b * NH + h) * SEQ) + qr0) * HD;
    const float* Kb = g_K + ((size_t)((b * NH + h) * SEQ)) * HD;
    const float* Vb = g_V + ((size_t)((b * NH + h) * SEQ)) * HD;
    const int* mb = mask + b * SEQ;

    uint32_t aQ[2][8][4];
#pragma unroll
    for (int mi = 0; mi < 2; mi++) {
        const float* Qm = Qp + (size_t)(16 * mi) * HD;
#pragma unroll
        for (int s = 0; s < 8; s++) {
            aQ[mi][s][0] = __float_as_uint(Qm[g * HD + 8 * s + tig]);
            aQ[mi][s][1] = __float_as_uint(Qm[(g + 8) * HD + 8 * s + tig]);
            aQ[mi][s][2] = __float_as_uint(Qm[g * HD + 8 * s + tig + 4]);
            aQ[mi][s][3] = __float_as_uint(Qm[(g + 8) * HD + 8 * s + tig + 4]);
        }
    }

    float oacc[2][8][4];
#pragma unroll
    for (int mi = 0; mi < 2; mi++)
#pragma unroll
        for (int j = 0; j < 8; j++)
#pragma unroll
            for (int c = 0; c < 4; c++) oacc[mi][j][c] = 0.f;
    float mrun[4] = {-1e30f, -1e30f, -1e30f, -1e30f};
    float lrun[4] = {0.f, 0.f, 0.f, 0.f};

    auto stage = [&](int kt, int buf) {
        const float* Kg = Kb + (size_t)kt * FKT * HD;
        const float* Vg = Vb + (size_t)kt * FKT * HD;
        const uint32_t dK = sbase + (F_KSM + buf * FKT * KVS) * 4;
        const uint32_t dV = sbase + (F_VSM + buf * FKT * KVS) * 4;
#pragma unroll
        for (int t = 0; t < 8; t++) {
            int idx = tid + t * 128;
            int row = idx >> 4;
            int c = idx & 15;
            CP_ASYNC16(dK + row * (KVS * 4) + c * 16, &Kg[row * HD + c * 4]);
            CP_ASYNC16(dV + row * (KVS * 4) + c * 16, &Vg[row * HD + c * 4]);
        }
        if (tid < FKT) {
            CP_ASYNC4(sbase + (F_MSK + buf * FKT + tid) * 4, &mb[kt * FKT + tid]);
        }
    };

    stage(0, 0);
    CP_ASYNC_COMMIT();

    uint32_t* Pw = (uint32_t*)(smf + F_PSM + w * 32 * KVS);

    for (int kt = 0; kt < FNT; kt++) {
        if (kt + 1 < FNT) {
            stage(kt + 1, (kt + 1) & 1);
            CP_ASYNC_COMMIT();
            CP_ASYNC_WAIT(1);
        } else {
            CP_ASYNC_WAIT(0);
        }
        __syncthreads();

        const int buf = kt & 1;
        const float* Kbuf = smf + F_KSM + buf * FKT * KVS;
        const float* Vbuf = smf + F_VSM + buf * FKT * KVS;
        const int* mk = smi + F_MSK + buf * FKT;

        float sc[2][8][4];
#pragma unroll
        for (int mi = 0; mi < 2; mi++)
#pragma unroll
            for (int j = 0; j < 8; j++)
#pragma unroll
                for (int c = 0; c < 4; c++) sc[mi][j][c] = 0.f;
#pragma unroll
        for (int s = 0; s < 8; s++) {
#pragma unroll
            for (int jn = 0; jn < 8; jn++) {
                uint32_t bf[2];
                bf[0] = __float_as_uint(Kbuf[(8 * jn + g) * KVS + 8 * s + tig]);
                bf[1] = __float_as_uint(Kbuf[(8 * jn + g) * KVS + 8 * s + tig + 4]);
                MMA_TF32(sc[0][jn], aQ[0][s], bf);
                MMA_TF32(sc[1][jn], aQ[1][s], bf);
            }
        }

#pragma unroll
        for (int mi = 0; mi < 2; mi++) {
#pragma unroll
            for (int jn = 0; jn < 8; jn++) {
                int2 mv = *(const int2*)&mk[8 * jn + 2 * tig];
                float ax = mv.x ? -1e30f : 0.f;
                float ay = mv.y ? -1e30f : 0.f;
                sc[mi][jn][0] = fmaf(sc[mi][jn][0], CS, ax);
                sc[mi][jn][1] = fmaf(sc[mi][jn][1], CS, ay);
                sc[mi][jn][2] = fmaf(sc[mi][jn][2], CS, ax);
                sc[mi][jn][3] = fmaf(sc[mi][jn][3], CS, ay);
            }
            float mx0 = -1e30f, mx1 = -1e30f;
#pragma unroll
            for (int jn = 0; jn < 8; jn++) {
                mx0 = fmaxf(mx0, fmaxf(sc[mi][jn][0], sc[mi][jn][1]));
                mx1 = fmaxf(mx1, fmaxf(sc[mi][jn][2], sc[mi][jn][3]));
            }
            mx0 = fmaxf(mx0, __shfl_xor_sync(0xFFFFFFFF, mx0, 1));
            mx0 = fmaxf(mx0, __shfl_xor_sync(0xFFFFFFFF, mx0, 2));
            mx1 = fmaxf(mx1, __shfl_xor_sync(0xFFFFFFFF, mx1, 1));
            mx1 = fmaxf(mx1, __shfl_xor_sync(0xFFFFFFFF, mx1, 2));

            const float nm0 = fmaxf(mrun[2 * mi], mx0);
            const float nm1 = fmaxf(mrun[2 * mi + 1], mx1);
            const float cor0 = fast_exp2(mrun[2 * mi] - nm0);
            const float cor1 = fast_exp2(mrun[2 * mi + 1] - nm1);
            mrun[2 * mi] = nm0;
            mrun[2 * mi + 1] = nm1;

            float s0 = 0.f, s1 = 0.f;
#pragma unroll
            for (int jn = 0; jn < 8; jn++) {
                sc[mi][jn][0] = fast_exp2(sc[mi][jn][0] - nm0);
                sc[mi][jn][1] = fast_exp2(sc[mi][jn][1] - nm0);
                sc[mi][jn][2] = fast_exp2(sc[mi][jn][2] - nm1);
                sc[mi][jn][3] = fast_exp2(sc[mi][jn][3] - nm1);
                s0 += sc[mi][jn][0] + sc[mi][jn][1];
                s1 += sc[mi][jn][2] + sc[mi][jn][3];
            }
            s0 += __shfl_xor_sync(0xFFFFFFFF, s0, 1);
            s0 += __shfl_xor_sync(0xFFFFFFFF, s0, 2);
            s1 += __shfl_xor_sync(0xFFFFFFFF, s1, 1);
            s1 += __shfl_xor_sync(0xFFFFFFFF, s1, 2);
            lrun[2 * mi] = lrun[2 * mi] * cor0 + s0;
            lrun[2 * mi + 1] = lrun[2 * mi + 1] * cor1 + s1;

#pragma unroll
            for (int j = 0; j < 8; j++) {
                oacc[mi][j][0] *= cor0;
                oacc[mi][j][1] *= cor0;
                oacc[mi][j][2] *= cor1;
                oacc[mi][j][3] *= cor1;
            }

#pragma unroll
            for (int jn = 0; jn < 8; jn++) {
                Pw[(16 * mi + g) * KVS + 8 * jn + 2 * tig]           = f2tf32(sc[mi][jn][0]);
                Pw[(16 * mi + g) * KVS + 8 * jn + 2 * tig + 1]       = f2tf32(sc[mi][jn][1]);
                Pw[(16 * mi + g + 8) * KVS + 8 * jn + 2 * tig]       = f2tf32(sc[mi][jn][2]);
                Pw[(16 * mi + g + 8) * KVS + 8 * jn + 2 * tig + 1]   = f2tf32(sc[mi][jn][3]);
            }
        }
        __syncwarp();

#pragma unroll
        for (int s2 = 0; s2 < 8; s2++) {
            uint32_t pa0[4], pa1[4];
            pa0[0] = Pw[g * KVS + 8 * s2 + tig];
            pa0[1] = Pw[(g + 8) * KVS + 8 * s2 + tig];
            pa0[2] = Pw[g * KVS + 8 * s2 + tig + 4];
            pa0[3] = Pw[(g + 8) * KVS + 8 * s2 + tig + 4];
            pa1[0] = Pw[(g + 16) * KVS + 8 * s2 + tig];
            pa1[1] = Pw[(g + 24) * KVS + 8 * s2 + tig];
            pa1[2] = Pw[(g + 16) * KVS + 8 * s2 + tig + 4];
            pa1[3] = Pw[(g + 24) * KVS + 8 * s2 + tig + 4];
#pragma unroll
            for (int jn2 = 0; jn2 < 8; jn2++) {
                uint32_t bf[2];
                bf[0] = __float_as_uint(Vbuf[(8 * s2 + tig) * KVS + 8 * jn2 + g]);
                bf[1] = __float_as_uint(Vbuf[(8 * s2 + tig + 4) * KVS + 8 * jn2 + g]);
                MMA_TF32(oacc[0][jn2], pa0, bf);
                MMA_TF32(oacc[1][jn2], pa1, bf);
            }
        }
        __syncthreads();
    }

#pragma unroll
    for (int mi = 0; mi < 2; mi++) {
        const float il0 = 1.f / lrun[2 * mi];
        const float il1 = 1.f / lrun[2 * mi + 1];
        float* O0 = Out + ((size_t)(b * SEQ + qr0 + 16 * mi + g)) * DIM + h * HD;
        float* O1 = Out + ((size_t)(b * SEQ + qr0 + 16 * mi + g + 8)) * DIM + h * HD;
#pragma unroll
        for (int jn2 = 0; jn2 < 8; jn2++) {
            float2 r0, r1;
            r0.x = __uint_as_float(f2tf32(oacc[mi][jn2][0] * il0));
            r0.y = __uint_as_float(f2tf32(oacc[mi][jn2][1] * il0));
            r1.x = __uint_as_float(f2tf32(oacc[mi][jn2][2] * il1));
            r1.y = __uint_as_float(f2tf32(oacc[mi][jn2][3] * il1));
            *(float2*)&O0[8 * jn2 + 2 * tig] = r0;
            *(float2*)&O1[8 * jn2 + 2 * tig] = r1;
        }
    }
}

// ---------------------------------------------------------------------------
extern "C" void kernel_launch(void* const* d_in, const int* in_sizes, int n_in,
                              void* d_out, int out_size) {
    const float* q  = (const float*)d_in[0];
    const float* k  = (const float*)d_in[1];
    const float* v  = (const float*)d_in[2];
    const int* mask = (const int*)d_in[3];
    const float* Wq = (const float*)d_in[4];
    const float* bq = (const float*)d_in[5];
    const float* Wk = (const float*)d_in[6];
    const float* bk = (const float*)d_in[7];
    const float* Wv = (const float*)d_in[8];
    const float* bv = (const float*)d_in[9];
    const float* Wo = (const float*)d_in[10];
    const float* bo = (const float*)d_in[11];
    float* out = (float*)d_out;

    float *pQ, *pK, *pV, *pA, *pWc, *pXc;
    cudaGetSymbolAddress((void**)&pQ, g_Q);
    cudaGetSymbolAddress((void**)&pK, g_K);
    cudaGetSymbolAddress((void**)&pV, g_V);
    cudaGetSymbolAddress((void**)&pA, g_A);
    cudaGetSymbolAddress((void**)&pWc, g_Wc);
    cudaGetSymbolAddress((void**)&pXc, g_Xc);

    cudaFuncSetAttribute(gemm_qkv, cudaFuncAttributeMaxDynamicSharedMemorySize, SM_GEMM_TOTAL);
    cudaFuncSetAttribute(gemm_out, cudaFuncAttributeMaxDynamicSharedMemorySize, SM_GEMM_TOTAL);
    cudaFuncSetAttribute(flash_attn_tc, cudaFuncAttributeMaxDynamicSharedMemorySize, FLASH_SMEM_BYTES);

    // --- fused tf32 pre-rounding (+ k-permute for qkv GEMM operands) ---
    const int WPAIR = DIM * DIM / 8;     // 131072
    const int XPAIR = MROWS * DIM / 8;   // 524288
    ConvArgs ca;
    ca.src[0] = Wq; ca.dst[0] = pWc + 0 * DIM * DIM; ca.npair[0] = WPAIR; ca.perm[0] = 1;
    ca.src[1] = Wk; ca.dst[1] = pWc + 1 * DIM * DIM; ca.npair[1] = WPAIR; ca.perm[1] = 1;
    ca.src[2] = Wv; ca.dst[2] = pWc + 2 * DIM * DIM; ca.npair[2] = WPAIR; ca.perm[2] = 1;
    ca.src[3] = Wo; ca.dst[3] = pWc + 3 * DIM * DIM; ca.npair[3] = WPAIR; ca.perm[3] = 0;
    ca.src[4] = q;  ca.dst[4] = pXc + 0 * (size_t)MROWS * DIM; ca.npair[4] = XPAIR; ca.perm[4] = 1;
    ca.src[5] = k;  ca.dst[5] = pXc + 1 * (size_t)MROWS * DIM; ca.npair[5] = XPAIR; ca.perm[5] = 1;
    ca.src[6] = v;  ca.dst[6] = pXc + 2 * (size_t)MROWS * DIM; ca.npair[6] = XPAIR; ca.perm[6] = 1;
    conv_tf32_all<<<dim3(XPAIR / 512, 7), 256>>>(ca);

    GemmArgs aq{pXc + 0 * (size_t)MROWS * DIM, pWc + 0 * DIM * DIM, bq, pQ};
    GemmArgs ak{pXc + 1 * (size_t)MROWS * DIM, pWc + 1 * DIM * DIM, bk, pK};
    GemmArgs av{pXc + 2 * (size_t)MROWS * DIM, pWc + 2 * DIM * DIM, bv, pV};

    dim3 gqkv(DIM / GBN, MROWS / GBM, 3);   // 384 CTAs
    gemm_qkv<<<gqkv, 256, SM_GEMM_TOTAL>>>(aq, ak, av);

    flash_attn_tc<<<dim3(SEQ / 128, NH, BATCH), 128, FLASH_SMEM_BYTES>>>(mask, pA);

    dim3 go(DIM / GBN, MROWS / GBM);        // 128 CTAs
    gemm_out<<<go, 512, SM_GEMM_TOTAL>>>(pA, pWc + 3 * DIM * DIM, bo, out);
}

// round 9
// speedup vs baseline: 1.0562x; 1.0562x over previous
#include <cuda_runtime.h>
#include <cstdint>

// Problem constants
#define BATCH 2
#define SEQ   2048
#define DIM   1024
#define NH    16
#define HD    64
#define MROWS (BATCH * SEQ)   // 4096

// Scratch (allocation-free rule: __device__ globals)
__device__ float g_Q[BATCH * NH * SEQ * HD];   // [b,h,s,hd] (tf32-rounded)
__device__ float g_K[BATCH * NH * SEQ * HD];   // (tf32-rounded)
__device__ float g_V[BATCH * NH * SEQ * HD];   // (tf32-rounded)
__device__ float g_A[BATCH * SEQ * DIM];       // attn out [b,s,h*hd] (tf32-rounded)
__device__ float g_Wc[4 * DIM * DIM];          // tf32-rounded Wq,Wk,Wv,Wo
__device__ float g_Xc[3 * MROWS * DIM];        // tf32-rounded q,k,v

// ---------------------------------------------------------------------------
// Helpers
// ---------------------------------------------------------------------------
__device__ __forceinline__ uint32_t smem_u32(const void* p) {
    uint32_t a;
    asm("{ .reg .u64 t; cvta.to.shared.u64 t, %1; cvt.u32.u64 %0, t; }" : "=r"(a) : "l"(p));
    return a;
}

#define CP_ASYNC16(dst, src) \
    asm volatile("cp.async.cg.shared.global [%0], [%1], 16;" :: "r"(dst), "l"(src))
#define CP_ASYNC4(dst, src) \
    asm volatile("cp.async.ca.shared.global [%0], [%1], 4;" :: "r"(dst), "l"(src))
#define CP_ASYNC_COMMIT() asm volatile("cp.async.commit_group;" ::: "memory")
#define CP_ASYNC_WAIT(n)  asm volatile("cp.async.wait_group %0;" :: "n"(n) : "memory")

__device__ __forceinline__ uint32_t f2tf32(float x) {
    uint32_t r;
    asm("cvt.rna.tf32.f32 %0, %1;" : "=r"(r) : "f"(x));
    return r;
}

#define MMA_TF32(d, av, bv)                                                   \
    asm volatile("mma.sync.aligned.m16n8k8.row.col.f32.tf32.tf32.f32 "        \
                 "{%0,%1,%2,%3}, {%4,%5,%6,%7}, {%8,%9}, {%0,%1,%2,%3};"      \
                 : "+f"((d)[0]), "+f"((d)[1]), "+f"((d)[2]), "+f"((d)[3])     \
                 : "r"((av)[0]), "r"((av)[1]), "r"((av)[2]), "r"((av)[3]),    \
                   "r"((bv)[0]), "r"((bv)[1]))

// Fast exp2 on the FMA pipe. Rel err ~3e-6.
__device__ __forceinline__ float fast_exp2(float x) {
    x = fmaxf(x, -126.0f);
    float t = x + 12582912.0f;            // 2^23 + 2^22
    float i = t - 12582912.0f;
    float f = x - i;
    float p = 1.3333558e-3f;
    p = fmaf(p, f, 9.6181291e-3f);
    p = fmaf(p, f, 5.5504109e-2f);
    p = fmaf(p, f, 2.4022651e-1f);
    p = fmaf(p, f, 6.9314718e-1f);
    p = fmaf(p, f, 1.0f);
    int ib = __float_as_int(t) << 23;     // == i << 23 exactly
    return __int_as_float(__float_as_int(p) + ib);
}

// ---------------------------------------------------------------------------
// Fused tf32 rounding pre-pass: all 7 arrays in ONE launch (identity layout).
// ---------------------------------------------------------------------------
struct ConvArgs {
    const float* src[7];
    float* dst[7];
    int n4[7];
};

__global__ __launch_bounds__(256) void conv_tf32_all(ConvArgs a) {
    const int seg = blockIdx.y;
    const float* src = a.src[seg];
    float* dst = a.dst[seg];
    const int n4 = a.n4[seg];
    int i0 = blockIdx.x * 1024 + threadIdx.x;
    if (i0 >= n4) return;
    float4 v[4];
    int idx[4];
#pragma unroll
    for (int t = 0; t < 4; t++) {
        idx[t] = i0 + t * 256;
        if (idx[t] < n4) v[t] = ((const float4*)src)[idx[t]];
    }
#pragma unroll
    for (int t = 0; t < 4; t++) {
        if (idx[t] < n4) {
            float4 r;
            r.x = __uint_as_float(f2tf32(v[t].x));
            r.y = __uint_as_float(f2tf32(v[t].y));
            r.z = __uint_as_float(f2tf32(v[t].z));
            r.w = __uint_as_float(f2tf32(v[t].w));
            ((float4*)dst)[idx[t]] = r;
        }
    }
}

// ---------------------------------------------------------------------------
// tf32 mma.sync GEMM: C = A @ W^T + bias. Pre-rounded tf32 inputs.
// CTA tile 128x128, BK=32, 256 threads = 8 warps (4m x 2n), warp tile 32x64.
// Small footprint -> 2 CTAs/SM (regs<=128, smem 64KB): barrier overlap.
// ---------------------------------------------------------------------------
#define GBM 128
#define GBN 128
#define GBK 32
#define NKT (DIM / GBK)                 // 32
#define SA_BYTES (GBM * GBK * 4)        // 16384
#define SB_BYTES (GBN * GBK * 4)        // 16384
#define SM_GEMM_TOTAL (2 * (SA_BYTES + SB_BYTES))   // 65536

struct GemmArgs {
    const float* A;
    const float* W;
    const float* bias;
    float* C;
};

template <int SPLIT_HEADS>
__device__ __forceinline__ void gemm_body(const float* __restrict__ A,
                                          const float* __restrict__ W,
                                          const float* __restrict__ bias,
                                          float* __restrict__ C) {
    extern __shared__ char smem[];
    const float* sAf = (const float*)smem;               // [2][128][32]
    const float* sBf = (const float*)(smem + 2 * SA_BYTES);
    const uint32_t sA = smem_u32(smem);
    const uint32_t sB = sA + 2 * SA_BYTES;

    const int tid = threadIdx.x;
    const int lane = tid & 31;
    const int wid = tid >> 5;      // 0..7
    const int wm = wid & 3;        // 0..3 (m: 4 x 32 = 128)
    const int wn = wid >> 2;       // 0..1 (n: 2 x 64 = 128)
    const int g = lane >> 2;
    const int tig = lane & 3;
    const int m0 = blockIdx.y * GBM;
    const int n0 = blockIdx.x * GBN;

    float acc[2][8][4];
#pragma unroll
    for (int i = 0; i < 2; i++)
#pragma unroll
        for (int j = 0; j < 8; j++)
#pragma unroll
            for (int c = 0; c < 4; c++) acc[i][j][c] = 0.f;

    auto stage = [&](int kt, int buf) {
        const int k0 = kt * GBK;
#pragma unroll
        for (int t = 0; t < 4; t++) {
            int idx = tid + t * 256;
            int row = idx >> 3;
            int c = idx & 7;
            uint32_t dst = sA + buf * SA_BYTES + row * 128 + ((c ^ (row & 7)) << 4);
            CP_ASYNC16(dst, &A[(size_t)(m0 + row) * DIM + k0 + c * 4]);
        }
#pragma unroll
        for (int t = 0; t < 4; t++) {
            int idx = tid + t * 256;
            int row = idx >> 3;
            int c = idx & 7;
            uint32_t dst = sB + buf * SB_BYTES + row * 128 + ((c ^ (row & 7)) << 4);
            CP_ASYNC16(dst, &W[(size_t)(n0 + row) * DIM + k0 + c * 4]);
        }
    };

    stage(0, 0);
    CP_ASYNC_COMMIT();

    for (int kt = 0; kt < NKT; kt++) {
        if (kt + 1 < NKT) {
            stage(kt + 1, (kt + 1) & 1);
            CP_ASYNC_COMMIT();
            CP_ASYNC_WAIT(1);
        } else {
            CP_ASYNC_WAIT(0);
        }
        __syncthreads();

        const float* Ab = sAf + (kt & 1) * (SA_BYTES / 4);
        const float* Bb = sBf + (kt & 1) * (SB_BYTES / 4);
#pragma unroll
        for (int s = 0; s < 4; s++) {
            const int k1 = s * 8 + tig;
            const int k2 = k1 + 4;
            uint32_t a[2][4];
#pragma unroll
            for (int i = 0; i < 2; i++) {
                int r1 = wm * 32 + i * 16 + g;
                int r2 = r1 + 8;
                a[i][0] = __float_as_uint(Ab[r1 * 32 + (k1 ^ ((r1 & 7) << 2))]);
                a[i][1] = __float_as_uint(Ab[r2 * 32 + (k1 ^ ((r2 & 7) << 2))]);
                a[i][2] = __float_as_uint(Ab[r1 * 32 + (k2 ^ ((r1 & 7) << 2))]);
                a[i][3] = __float_as_uint(Ab[r2 * 32 + (k2 ^ ((r2 & 7) << 2))]);
            }
            uint32_t bf[8][2];
#pragma unroll
            for (int j = 0; j < 8; j++) {
                int rn = wn * 64 + j * 8 + g;
                bf[j][0] = __float_as_uint(Bb[rn * 32 + (k1 ^ ((rn & 7) << 2))]);
                bf[j][1] = __float_as_uint(Bb[rn * 32 + (k2 ^ ((rn & 7) << 2))]);
            }
#pragma unroll
            for (int i = 0; i < 2; i++)
#pragma unroll
                for (int j = 0; j < 8; j++) MMA_TF32(acc[i][j], a[i], bf[j]);
        }
        __syncthreads();
    }

#pragma unroll
    for (int i = 0; i < 2; i++) {
        const int m1 = m0 + wm * 32 + i * 16 + g;
        const int m2 = m1 + 8;
#pragma unroll
        for (int j = 0; j < 8; j++) {
            const int n = n0 + wn * 64 + j * 8 + tig * 2;
            const float2 bb = *(const float2*)&bias[n];
            float2 r1, r2;
            if (SPLIT_HEADS) {
                r1.x = __uint_as_float(f2tf32(acc[i][j][0] + bb.x));
                r1.y = __uint_as_float(f2tf32(acc[i][j][1] + bb.y));
                r2.x = __uint_as_float(f2tf32(acc[i][j][2] + bb.x));
                r2.y = __uint_as_float(f2tf32(acc[i][j][3] + bb.y));
                int h = n >> 6;
                int hd = n & (HD - 1);
                {
                    int b = m1 >> 11, sq = m1 & (SEQ - 1);
                    *(float2*)&C[((size_t)((b * NH + h) * SEQ + sq)) * HD + hd] = r1;
                }
                {
                    int b = m2 >> 11, sq = m2 & (SEQ - 1);
                    *(float2*)&C[((size_t)((b * NH + h) * SEQ + sq)) * HD + hd] = r2;
                }
            } else {
                r1.x = acc[i][j][0] + bb.x;
                r1.y = acc[i][j][1] + bb.y;
                r2.x = acc[i][j][2] + bb.x;
                r2.y = acc[i][j][3] + bb.y;
                *(float2*)&C[(size_t)m1 * DIM + n] = r1;
                *(float2*)&C[(size_t)m2 * DIM + n] = r2;
            }
        }
    }
}

__global__ __launch_bounds__(256, 2) void gemm_qkv(GemmArgs a0, GemmArgs a1, GemmArgs a2) {
    const GemmArgs& a = (blockIdx.z == 0) ? a0 : (blockIdx.z == 1) ? a1 : a2;
    gemm_body<1>(a.A, a.W, a.bias, a.C);
}

__global__ __launch_bounds__(256, 2) void gemm_out(const float* __restrict__ A,
                                                   const float* __restrict__ W,
                                                   const float* __restrict__ bias,
                                                   float* __restrict__ C) {
    gemm_body<0>(A, W, bias, C);
}

// ---------------------------------------------------------------------------
// Tensor-core flash attention (tf32 mma.sync), M=32 rows per warp. Unchanged
// from R6 (proven config).
// ---------------------------------------------------------------------------
#define FKT 64
#define KVS 72          // smem row stride (floats)
#define FNT (SEQ / FKT) // 32

#define F_KSM 0
#define F_VSM (2 * FKT * KVS)                 // 9216
#define F_PSM (F_VSM + 2 * FKT * KVS)         // 18432
#define F_MSK (F_PSM + 128 * KVS)             // 27648 (int region)
#define F_TOTAL_FLOATS (F_MSK + 2 * FKT)      // 27776
#define FLASH_SMEM_BYTES (F_TOTAL_FLOATS * 4) // 111104

#define CS 0.18033688f  // 0.125 * log2(e)

__global__ __launch_bounds__(128) void flash_attn_tc(const int* __restrict__ mask,
                                                     float* __restrict__ Out) {
    extern __shared__ char smem[];
    float* smf = (float*)smem;
    int* smi = (int*)smem;
    const uint32_t sbase = smem_u32(smem);

    const int b = blockIdx.z;
    const int h = blockIdx.y;
    const int tid = threadIdx.x;
    const int w = tid >> 5;
    const int lane = tid & 31;
    const int g = lane >> 2;
    const int tig = lane & 3;
    const int qr0 = blockIdx.x * 128 + w * 32;

    const float* Qp = g_Q + ((size_t)((b * NH + h) * SEQ) + qr0) * HD;
    const float* Kb = g_K + ((size_t)((b * NH + h) * SEQ)) * HD;
    const float* Vb = g_V + ((size_t)((b * NH + h) * SEQ)) * HD;
    const int* mb = mask + b * SEQ;

    uint32_t aQ[2][8][4];
#pragma unroll
    for (int mi = 0; mi < 2; mi++) {
        const float* Qm = Qp + (size_t)(16 * mi) * HD;
#pragma unroll
        for (int s = 0; s < 8; s++) {
            aQ[mi][s][0] = __float_as_uint(Qm[g * HD + 8 * s + tig]);
            aQ[mi][s][1] = __float_as_uint(Qm[(g + 8) * HD + 8 * s + tig]);
            aQ[mi][s][2] = __float_as_uint(Qm[g * HD + 8 * s + tig + 4]);
            aQ[mi][s][3] = __float_as_uint(Qm[(g + 8) * HD + 8 * s + tig + 4]);
        }
    }

    float oacc[2][8][4];
#pragma unroll
    for (int mi = 0; mi < 2; mi++)
#pragma unroll
        for (int j = 0; j < 8; j++)
#pragma unroll
            for (int c = 0; c < 4; c++) oacc[mi][j][c] = 0.f;
    float mrun[4] = {-1e30f, -1e30f, -1e30f, -1e30f};
    float lrun[4] = {0.f, 0.f, 0.f, 0.f};

    auto stage = [&](int kt, int buf) {
        const float* Kg = Kb + (size_t)kt * FKT * HD;
        const float* Vg = Vb + (size_t)kt * FKT * HD;
        const uint32_t dK = sbase + (F_KSM + buf * FKT * KVS) * 4;
        const uint32_t dV = sbase + (F_VSM + buf * FKT * KVS) * 4;
#pragma unroll
        for (int t = 0; t < 8; t++) {
            int idx = tid + t * 128;
            int row = idx >> 4;
            int c = idx & 15;
            CP_ASYNC16(dK + row * (KVS * 4) + c * 16, &Kg[row * HD + c * 4]);
            CP_ASYNC16(dV + row * (KVS * 4) + c * 16, &Vg[row * HD + c * 4]);
        }
        if (tid < FKT) {
            CP_ASYNC4(sbase + (F_MSK + buf * FKT + tid) * 4, &mb[kt * FKT + tid]);
        }
    };

    stage(0, 0);
    CP_ASYNC_COMMIT();

    uint32_t* Pw = (uint32_t*)(smf + F_PSM + w * 32 * KVS);

    for (int kt = 0; kt < FNT; kt++) {
        if (kt + 1 < FNT) {
            stage(kt + 1, (kt + 1) & 1);
            CP_ASYNC_COMMIT();
            CP_ASYNC_WAIT(1);
        } else {
            CP_ASYNC_WAIT(0);
        }
        __syncthreads();

        const int buf = kt & 1;
        const float* Kbuf = smf + F_KSM + buf * FKT * KVS;
        const float* Vbuf = smf + F_VSM + buf * FKT * KVS;
        const int* mk = smi + F_MSK + buf * FKT;

        float sc[2][8][4];
#pragma unroll
        for (int mi = 0; mi < 2; mi++)
#pragma unroll
            for (int j = 0; j < 8; j++)
#pragma unroll
                for (int c = 0; c < 4; c++) sc[mi][j][c] = 0.f;
#pragma unroll
        for (int s = 0; s < 8; s++) {
#pragma unroll
            for (int jn = 0; jn < 8; jn++) {
                uint32_t bf[2];
                bf[0] = __float_as_uint(Kbuf[(8 * jn + g) * KVS + 8 * s + tig]);
                bf[1] = __float_as_uint(Kbuf[(8 * jn + g) * KVS + 8 * s + tig + 4]);
                MMA_TF32(sc[0][jn], aQ[0][s], bf);
                MMA_TF32(sc[1][jn], aQ[1][s], bf);
            }
        }

#pragma unroll
        for (int mi = 0; mi < 2; mi++) {
#pragma unroll
            for (int jn = 0; jn < 8; jn++) {
                int2 mv = *(const int2*)&mk[8 * jn + 2 * tig];
                float ax = mv.x ? -1e30f : 0.f;
                float ay = mv.y ? -1e30f : 0.f;
                sc[mi][jn][0] = fmaf(sc[mi][jn][0], CS, ax);
                sc[mi][jn][1] = fmaf(sc[mi][jn][1], CS, ay);
                sc[mi][jn][2] = fmaf(sc[mi][jn][2], CS, ax);
                sc[mi][jn][3] = fmaf(sc[mi][jn][3], CS, ay);
            }
            float mx0 = -1e30f, mx1 = -1e30f;
#pragma unroll
            for (int jn = 0; jn < 8; jn++) {
                mx0 = fmaxf(mx0, fmaxf(sc[mi][jn][0], sc[mi][jn][1]));
                mx1 = fmaxf(mx1, fmaxf(sc[mi][jn][2], sc[mi][jn][3]));
            }
            mx0 = fmaxf(mx0, __shfl_xor_sync(0xFFFFFFFF, mx0, 1));
            mx0 = fmaxf(mx0, __shfl_xor_sync(0xFFFFFFFF, mx0, 2));
            mx1 = fmaxf(mx1, __shfl_xor_sync(0xFFFFFFFF, mx1, 1));
            mx1 = fmaxf(mx1, __shfl_xor_sync(0xFFFFFFFF, mx1, 2));

            const float nm0 = fmaxf(mrun[2 * mi], mx0);
            const float nm1 = fmaxf(mrun[2 * mi + 1], mx1);
            const float cor0 = fast_exp2(mrun[2 * mi] - nm0);
            const float cor1 = fast_exp2(mrun[2 * mi + 1] - nm1);
            mrun[2 * mi] = nm0;
            mrun[2 * mi + 1] = nm1;

            float s0 = 0.f, s1 = 0.f;
#pragma unroll
            for (int jn = 0; jn < 8; jn++) {
                sc[mi][jn][0] = fast_exp2(sc[mi][jn][0] - nm0);
                sc[mi][jn][1] = fast_exp2(sc[mi][jn][1] - nm0);
                sc[mi][jn][2] = fast_exp2(sc[mi][jn][2] - nm1);
                sc[mi][jn][3] = fast_exp2(sc[mi][jn][3] - nm1);
                s0 += sc[mi][jn][0] + sc[mi][jn][1];
                s1 += sc[mi][jn][2] + sc[mi][jn][3];
            }
            s0 += __shfl_xor_sync(0xFFFFFFFF, s0, 1);
            s0 += __shfl_xor_sync(0xFFFFFFFF, s0, 2);
            s1 += __shfl_xor_sync(0xFFFFFFFF, s1, 1);
            s1 += __shfl_xor_sync(0xFFFFFFFF, s1, 2);
            lrun[2 * mi] = lrun[2 * mi] * cor0 + s0;
            lrun[2 * mi + 1] = lrun[2 * mi + 1] * cor1 + s1;

#pragma unroll
            for (int j = 0; j < 8; j++) {
                oacc[mi][j][0] *= cor0;
                oacc[mi][j][1] *= cor0;
                oacc[mi][j][2] *= cor1;
                oacc[mi][j][3] *= cor1;
            }

#pragma unroll
            for (int jn = 0; jn < 8; jn++) {
                Pw[(16 * mi + g) * KVS + 8 * jn + 2 * tig]           = f2tf32(sc[mi][jn][0]);
                Pw[(16 * mi + g) * KVS + 8 * jn + 2 * tig + 1]       = f2tf32(sc[mi][jn][1]);
                Pw[(16 * mi + g + 8) * KVS + 8 * jn + 2 * tig]       = f2tf32(sc[mi][jn][2]);
                Pw[(16 * mi + g + 8) * KVS + 8 * jn + 2 * tig + 1]   = f2tf32(sc[mi][jn][3]);
            }
        }
        __syncwarp();

#pragma unroll
        for (int s2 = 0; s2 < 8; s2++) {
            uint32_t pa0[4], pa1[4];
            pa0[0] = Pw[g * KVS + 8 * s2 + tig];
            pa0[1] = Pw[(g + 8) * KVS + 8 * s2 + tig];
            pa0[2] = Pw[g * KVS + 8 * s2 + tig + 4];
            pa0[3] = Pw[(g + 8) * KVS + 8 * s2 + tig + 4];
            pa1[0] = Pw[(g + 16) * KVS + 8 * s2 + tig];
            pa1[1] = Pw[(g + 24) * KVS + 8 * s2 + tig];
            pa1[2] = Pw[(g + 16) * KVS + 8 * s2 + tig + 4];
            pa1[3] = Pw[(g + 24) * KVS + 8 * s2 + tig + 4];
#pragma unroll
            for (int jn2 = 0; jn2 < 8; jn2++) {
                uint32_t bf[2];
                bf[0] = __float_as_uint(Vbuf[(8 * s2 + tig) * KVS + 8 * jn2 + g]);
                bf[1] = __float_as_uint(Vbuf[(8 * s2 + tig + 4) * KVS + 8 * jn2 + g]);
                MMA_TF32(oacc[0][jn2], pa0, bf);
                MMA_TF32(oacc[1][jn2], pa1, bf);
            }
        }
        __syncthreads();
    }

#pragma unroll
    for (int mi = 0; mi < 2; mi++) {
        const float il0 = 1.f / lrun[2 * mi];
        const float il1 = 1.f / lrun[2 * mi + 1];
        float* O0 = Out + ((size_t)(b * SEQ + qr0 + 16 * mi + g)) * DIM + h * HD;
        float* O1 = Out + ((size_t)(b * SEQ + qr0 + 16 * mi + g + 8)) * DIM + h * HD;
#pragma unroll
        for (int jn2 = 0; jn2 < 8; jn2++) {
            float2 r0, r1;
            r0.x = __uint_as_float(f2tf32(oacc[mi][jn2][0] * il0));
            r0.y = __uint_as_float(f2tf32(oacc[mi][jn2][1] * il0));
            r1.x = __uint_as_float(f2tf32(oacc[mi][jn2][2] * il1));
            r1.y = __uint_as_float(f2tf32(oacc[mi][jn2][3] * il1));
            *(float2*)&O0[8 * jn2 + 2 * tig] = r0;
            *(float2*)&O1[8 * jn2 + 2 * tig] = r1;
        }
    }
}

// ---------------------------------------------------------------------------
extern "C" void kernel_launch(void* const* d_in, const int* in_sizes, int n_in,
                              void* d_out, int out_size) {
    const float* q  = (const float*)d_in[0];
    const float* k  = (const float*)d_in[1];
    const float* v  = (const float*)d_in[2];
    const int* mask = (const int*)d_in[3];
    const float* Wq = (const float*)d_in[4];
    const float* bq = (const float*)d_in[5];
    const float* Wk = (const float*)d_in[6];
    const float* bk = (const float*)d_in[7];
    const float* Wv = (const float*)d_in[8];
    const float* bv = (const float*)d_in[9];
    const float* Wo = (const float*)d_in[10];
    const float* bo = (const float*)d_in[11];
    float* out = (float*)d_out;

    float *pQ, *pK, *pV, *pA, *pWc, *pXc;
    cudaGetSymbolAddress((void**)&pQ, g_Q);
    cudaGetSymbolAddress((void**)&pK, g_K);
    cudaGetSymbolAddress((void**)&pV, g_V);
    cudaGetSymbolAddress((void**)&pA, g_A);
    cudaGetSymbolAddress((void**)&pWc, g_Wc);
    cudaGetSymbolAddress((void**)&pXc, g_Xc);

    cudaFuncSetAttribute(gemm_qkv, cudaFuncAttributeMaxDynamicSharedMemorySize, SM_GEMM_TOTAL);
    cudaFuncSetAttribute(gemm_out, cudaFuncAttributeMaxDynamicSharedMemorySize, SM_GEMM_TOTAL);
    cudaFuncSetAttribute(flash_attn_tc, cudaFuncAttributeMaxDynamicSharedMemorySize, FLASH_SMEM_BYTES);

    // --- fused tf32 pre-rounding: one launch for all 7 arrays ---
    const int W4 = DIM * DIM / 4;       // 262144
    const int X4 = MROWS * DIM / 4;     // 1048576
    ConvArgs ca;
    ca.src[0] = Wq; ca.dst[0] = pWc + 0 * DIM * DIM; ca.n4[0] = W4;
    ca.src[1] = Wk; ca.dst[1] = pWc + 1 * DIM * DIM; ca.n4[1] = W4;
    ca.src[2] = Wv; ca.dst[2] = pWc + 2 * DIM * DIM; ca.n4[2] = W4;
    ca.src[3] = Wo; ca.dst[3] = pWc + 3 * DIM * DIM; ca.n4[3] = W4;
    ca.src[4] = q;  ca.dst[4] = pXc + 0 * (size_t)MROWS * DIM; ca.n4[4] = X4;
    ca.src[5] = k;  ca.dst[5] = pXc + 1 * (size_t)MROWS * DIM; ca.n4[5] = X4;
    ca.src[6] = v;  ca.dst[6] = pXc + 2 * (size_t)MROWS * DIM; ca.n4[6] = X4;
    conv_tf32_all<<<dim3(X4 / 1024, 7), 256>>>(ca);

    GemmArgs aq{pXc + 0 * (size_t)MROWS * DIM, pWc + 0 * DIM * DIM, bq, pQ};
    GemmArgs ak{pXc + 1 * (size_t)MROWS * DIM, pWc + 1 * DIM * DIM, bk, pK};
    GemmArgs av{pXc + 2 * (size_t)MROWS * DIM, pWc + 2 * DIM * DIM, bv, pV};

    dim3 gqkv(DIM / GBN, MROWS / GBM, 3);   // (8, 32, 3) = 768 CTAs
    gemm_qkv<<<gqkv, 256, SM_GEMM_TOTAL>>>(aq, ak, av);

    flash_attn_tc<<<dim3(SEQ / 128, NH, BATCH), 128, FLASH_SMEM_BYTES>>>(mask, pA);

    dim3 go(DIM / GBN, MROWS / GBM);        // (8, 32) = 256 CTAs
    gemm_out<<<go, 256, SM_GEMM_TOTAL>>>(pA, pWc + 3 * DIM * DIM, bo, out);
}

// round 10
// speedup vs baseline: 1.6968x; 1.6065x over previous
#include <cuda_runtime.h>
#include <cuda_fp16.h>
#include <cstdint>

// Problem constants
#define BATCH 2
#define SEQ   2048
#define DIM   1024
#define NH    16
#define HD    64
#define MROWS (BATCH * SEQ)   // 4096

// Scratch (allocation-free rule: __device__ globals)
__device__ __half g_Q[BATCH * NH * SEQ * HD];  // [b,h,s,hd] fp16
__device__ __half g_K[BATCH * NH * SEQ * HD];
__device__ __half g_V[BATCH * NH * SEQ * HD];
__device__ __half g_A[BATCH * SEQ * DIM];      // attn out [b,s,h*hd] fp16
__device__ __half g_Wh[4 * DIM * DIM];         // fp16 Wq,Wk,Wv,Wo
__device__ __half g_Xh[3 * (size_t)MROWS * DIM]; // fp16 q,k,v

// ---------------------------------------------------------------------------
// Helpers
// ---------------------------------------------------------------------------
__device__ __forceinline__ uint32_t smem_u32(const void* p) {
    uint32_t a;
    asm("{ .reg .u64 t; cvta.to.shared.u64 t, %1; cvt.u32.u64 %0, t; }" : "=r"(a) : "l"(p));
    return a;
}

#define CP_ASYNC16(dst, src) \
    asm volatile("cp.async.cg.shared.global [%0], [%1], 16;" :: "r"(dst), "l"(src))
#define CP_ASYNC4(dst, src) \
    asm volatile("cp.async.ca.shared.global [%0], [%1], 4;" :: "r"(dst), "l"(src))
#define CP_ASYNC_COMMIT() asm volatile("cp.async.commit_group;" ::: "memory")
#define CP_ASYNC_WAIT(n)  asm volatile("cp.async.wait_group %0;" :: "n"(n) : "memory")

// fp16 MMA, fp32 accumulate: m16n8k16
#define MMA_F16(d, av, bv)                                                    \
    asm volatile("mma.sync.aligned.m16n8k16.row.col.f32.f16.f16.f32 "         \
                 "{%0,%1,%2,%3}, {%4,%5,%6,%7}, {%8,%9}, {%0,%1,%2,%3};"      \
                 : "+f"((d)[0]), "+f"((d)[1]), "+f"((d)[2]), "+f"((d)[3])     \
                 : "r"((av)[0]), "r"((av)[1]), "r"((av)[2]), "r"((av)[3]),    \
                   "r"((bv)[0]), "r"((bv)[1]))

__device__ __forceinline__ uint32_t pack_h2(float a, float b) {
    __half2 h = __floats2half2_rn(a, b);
    return *(uint32_t*)&h;
}

// Fast exp2 on the FMA pipe. Rel err ~3e-6.
__device__ __forceinline__ float fast_exp2(float x) {
    x = fmaxf(x, -126.0f);
    float t = x + 12582912.0f;            // 2^23 + 2^22
    float i = t - 12582912.0f;
    float f = x - i;
    float p = 1.3333558e-3f;
    p = fmaf(p, f, 9.6181291e-3f);
    p = fmaf(p, f, 5.5504109e-2f);
    p = fmaf(p, f, 2.4022651e-1f);
    p = fmaf(p, f, 6.9314718e-1f);
    p = fmaf(p, f, 1.0f);
    int ib = __float_as_int(t) << 23;     // == i << 23 exactly
    return __int_as_float(__float_as_int(p) + ib);
}

// ---------------------------------------------------------------------------
// Fused fp32 -> fp16 conversion pre-pass (7 arrays, one launch).
// Each thread handles 4 groups of 8 floats.
// ---------------------------------------------------------------------------
struct ConvArgs {
    const float* src[7];
    __half* dst[7];
    int n8[7];     // number of 8-float groups
};

__global__ __launch_bounds__(256) void conv_f16_all(ConvArgs a) {
    const int seg = blockIdx.y;
    const float* src = a.src[seg];
    __half* dst = a.dst[seg];
    const int n8 = a.n8[seg];
    int i0 = blockIdx.x * 1024 + threadIdx.x;
    if (i0 >= n8) return;
#pragma unroll
    for (int t = 0; t < 4; t++) {
        int idx = i0 + t * 256;
        if (idx < n8) {
            float4 v0 = ((const float4*)src)[2 * idx];
            float4 v1 = ((const float4*)src)[2 * idx + 1];
            uint4 o;
            o.x = pack_h2(v0.x, v0.y);
            o.y = pack_h2(v0.z, v0.w);
            o.z = pack_h2(v1.x, v1.y);
            o.w = pack_h2(v1.z, v1.w);
            ((uint4*)dst)[idx] = o;
        }
    }
}

// ---------------------------------------------------------------------------
// fp16 mma.sync GEMM: C = A @ W^T + bias. fp16 operands, fp32 accumulate.
// CTA tile 128x128, BK=64 (halves), 256 threads = 8 warps (4m x 2n), 32x64.
// 128B rows (64 halves) with 16B-chunk XOR swizzle. 2 CTAs/SM.
// ---------------------------------------------------------------------------
#define GBM 128
#define GBN 128
#define GBK 64
#define NKT (DIM / GBK)                 // 16
#define SA_BYTES (GBM * GBK * 2)        // 16384
#define SB_BYTES (GBN * GBK * 2)        // 16384
#define SM_GEMM_TOTAL (2 * (SA_BYTES + SB_BYTES))   // 65536

struct GemmArgs {
    const __half* A;
    const __half* W;
    const float* bias;
    void* C;
};

__device__ __forceinline__ uint32_t lds32_sw(const char* base, int row, int chunk, int off) {
    return *(const uint32_t*)(base + row * 128 + (((chunk) ^ (row & 7)) << 4) + off);
}

template <int SPLIT_HEADS>
__device__ __forceinline__ void gemm_body(const __half* __restrict__ A,
                                          const __half* __restrict__ W,
                                          const float* __restrict__ bias,
                                          void* __restrict__ Cv) {
    extern __shared__ char smem[];
    const char* sAc = smem;
    const char* sBc = smem + 2 * SA_BYTES;
    const uint32_t sA = smem_u32(smem);
    const uint32_t sB = sA + 2 * SA_BYTES;

    const int tid = threadIdx.x;
    const int lane = tid & 31;
    const int wid = tid >> 5;      // 0..7
    const int wm = wid & 3;        // 0..3 (m: 4 x 32)
    const int wn = wid >> 2;       // 0..1 (n: 2 x 64)
    const int g = lane >> 2;
    const int tig = lane & 3;
    const int m0 = blockIdx.y * GBM;
    const int n0 = blockIdx.x * GBN;

    float acc[2][8][4];
#pragma unroll
    for (int i = 0; i < 2; i++)
#pragma unroll
        for (int j = 0; j < 8; j++)
#pragma unroll
            for (int c = 0; c < 4; c++) acc[i][j][c] = 0.f;

    auto stage = [&](int kt, int buf) {
        const int k0 = kt * GBK;    // halves
#pragma unroll
        for (int t = 0; t < 4; t++) {
            int idx = tid + t * 256;
            int row = idx >> 3;
            int c = idx & 7;
            uint32_t dst = sA + buf * SA_BYTES + row * 128 + ((c ^ (row & 7)) << 4);
            CP_ASYNC16(dst, &A[(size_t)(m0 + row) * DIM + k0 + c * 8]);
        }
#pragma unroll
        for (int t = 0; t < 4; t++) {
            int idx = tid + t * 256;
            int row = idx >> 3;
            int c = idx & 7;
            uint32_t dst = sB + buf * SB_BYTES + row * 128 + ((c ^ (row & 7)) << 4);
            CP_ASYNC16(dst, &W[(size_t)(n0 + row) * DIM + k0 + c * 8]);
        }
    };

    stage(0, 0);
    CP_ASYNC_COMMIT();

    for (int kt = 0; kt < NKT; kt++) {
        if (kt + 1 < NKT) {
            stage(kt + 1, (kt + 1) & 1);
            CP_ASYNC_COMMIT();
            CP_ASYNC_WAIT(1);
        } else {
            CP_ASYNC_WAIT(0);
        }
        __syncthreads();

        const char* Ab = sAc + (kt & 1) * SA_BYTES;
        const char* Bb = sBc + (kt & 1) * SB_BYTES;
#pragma unroll
        for (int s = 0; s < 4; s++) {
            const int c0 = 2 * s;
            const int off = tig * 4;
            uint32_t a[2][4];
#pragma unroll
            for (int i = 0; i < 2; i++) {
                int r1 = wm * 32 + i * 16 + g;
                int r2 = r1 + 8;
                a[i][0] = lds32_sw(Ab, r1, c0, off);
                a[i][1] = lds32_sw(Ab, r2, c0, off);
                a[i][2] = lds32_sw(Ab, r1, c0 + 1, off);
                a[i][3] = lds32_sw(Ab, r2, c0 + 1, off);
            }
            uint32_t bf[8][2];
#pragma unroll
            for (int j = 0; j < 8; j++) {
                int rn = wn * 64 + j * 8 + g;
                bf[j][0] = lds32_sw(Bb, rn, c0, off);
                bf[j][1] = lds32_sw(Bb, rn, c0 + 1, off);
            }
#pragma unroll
            for (int i = 0; i < 2; i++)
#pragma unroll
                for (int j = 0; j < 8; j++) MMA_F16(acc[i][j], a[i], bf[j]);
        }
        __syncthreads();
    }

#pragma unroll
    for (int i = 0; i < 2; i++) {
        const int m1 = m0 + wm * 32 + i * 16 + g;
        const int m2 = m1 + 8;
#pragma unroll
        for (int j = 0; j < 8; j++) {
            const int n = n0 + wn * 64 + j * 8 + tig * 2;
            const float2 bb = *(const float2*)&bias[n];
            if (SPLIT_HEADS) {
                __half* C = (__half*)Cv;
                uint32_t h1 = pack_h2(acc[i][j][0] + bb.x, acc[i][j][1] + bb.y);
                uint32_t h2 = pack_h2(acc[i][j][2] + bb.x, acc[i][j][3] + bb.y);
                int h = n >> 6;
                int hd = n & (HD - 1);
                {
                    int b = m1 >> 11, sq = m1 & (SEQ - 1);
                    *(uint32_t*)&C[((size_t)((b * NH + h) * SEQ + sq)) * HD + hd] = h1;
                }
                {
                    int b = m2 >> 11, sq = m2 & (SEQ - 1);
                    *(uint32_t*)&C[((size_t)((b * NH + h) * SEQ + sq)) * HD + hd] = h2;
                }
            } else {
                float* C = (float*)Cv;
                float2 r1, r2;
                r1.x = acc[i][j][0] + bb.x;
                r1.y = acc[i][j][1] + bb.y;
                r2.x = acc[i][j][2] + bb.x;
                r2.y = acc[i][j][3] + bb.y;
                *(float2*)&C[(size_t)m1 * DIM + n] = r1;
                *(float2*)&C[(size_t)m2 * DIM + n] = r2;
            }
        }
    }
}

__global__ __launch_bounds__(256, 2) void gemm_qkv(GemmArgs a0, GemmArgs a1, GemmArgs a2) {
    const GemmArgs& a = (blockIdx.z == 0) ? a0 : (blockIdx.z == 1) ? a1 : a2;
    gemm_body<1>(a.A, a.W, a.bias, a.C);
}

__global__ __launch_bounds__(256, 2) void gemm_out(const __half* __restrict__ A,
                                                   const __half* __restrict__ W,
                                                   const float* __restrict__ bias,
                                                   float* __restrict__ C) {
    gemm_body<0>(A, W, bias, C);
}

// ---------------------------------------------------------------------------
// Tensor-core flash attention, fp16 mma (fp32 accumulate + fp32 softmax).
// 128 thr (4 warps), 128 q-rows/CTA, M=32/warp. KV tiles of 64 rows,
// cp.async double-buffered. Rows padded to 144B (conflict-free).
// ---------------------------------------------------------------------------
#define FKT 64
#define FNT (SEQ / FKT)   // 32
#define KVROW 144         // bytes per KV/P row (64 halves + 8 pad)
#define KBUF (FKT * KVROW)        // 9216
#define B_K 0
#define B_V (2 * KBUF)            // 18432
#define B_P (4 * KBUF)            // 36864
#define B_M (B_P + 128 * KVROW)   // 55296
#define FLASH_SMEM_BYTES (B_M + 2 * FKT * 4)  // 55808

#define CS 0.18033688f  // 0.125 * log2(e)

__global__ __launch_bounds__(128) void flash_attn_tc(const int* __restrict__ mask,
                                                     __half* __restrict__ Out) {
    extern __shared__ char smem[];
    const uint32_t sbase = smem_u32(smem);

    const int b = blockIdx.z;
    const int h = blockIdx.y;
    const int tid = threadIdx.x;
    const int w = tid >> 5;
    const int lane = tid & 31;
    const int g = lane >> 2;
    const int tig = lane & 3;
    const int qr0 = blockIdx.x * 128 + w * 32;

    const __half* Qp = g_Q + ((size_t)((b * NH + h) * SEQ) + qr0) * HD;
    const __half* Kb = g_K + ((size_t)((b * NH + h) * SEQ)) * HD;
    const __half* Vb = g_V + ((size_t)((b * NH + h) * SEQ)) * HD;
    const int* mb = mask + b * SEQ;

    // Persistent Q A-fragments (fp16, half2-packed)
    uint32_t aQ[2][4][4];
#pragma unroll
    for (int mi = 0; mi < 2; mi++) {
        const __half* Qm = Qp + (size_t)(16 * mi) * HD;
#pragma unroll
        for (int s = 0; s < 4; s++) {
            aQ[mi][s][0] = *(const uint32_t*)&Qm[g * HD + s * 16 + tig * 2];
            aQ[mi][s][1] = *(const uint32_t*)&Qm[(g + 8) * HD + s * 16 + tig * 2];
            aQ[mi][s][2] = *(const uint32_t*)&Qm[g * HD + s * 16 + 8 + tig * 2];
            aQ[mi][s][3] = *(const uint32_t*)&Qm[(g + 8) * HD + s * 16 + 8 + tig * 2];
        }
    }

    float oacc[2][8][4];
#pragma unroll
    for (int mi = 0; mi < 2; mi++)
#pragma unroll
        for (int j = 0; j < 8; j++)
#pragma unroll
            for (int c = 0; c < 4; c++) oacc[mi][j][c] = 0.f;
    float mrun[4] = {-1e30f, -1e30f, -1e30f, -1e30f};
    float lrun[4] = {0.f, 0.f, 0.f, 0.f};

    auto stage = [&](int kt, int buf) {
        const __half* Kg = Kb + (size_t)kt * FKT * HD;
        const __half* Vg = Vb + (size_t)kt * FKT * HD;
        const uint32_t dK = sbase + B_K + buf * KBUF;
        const uint32_t dV = sbase + B_V + buf * KBUF;
#pragma unroll
        for (int t = 0; t < 4; t++) {
            int idx = tid + t * 128;       // 0..511
            int row = idx >> 3;            // 0..63
            int c = idx & 7;               // 16B chunk
            CP_ASYNC16(dK + row * KVROW + c * 16, &Kg[row * HD + c * 8]);
            CP_ASYNC16(dV + row * KVROW + c * 16, &Vg[row * HD + c * 8]);
        }
        if (tid < FKT) {
            CP_ASYNC4(sbase + B_M + buf * (FKT * 4) + tid * 4, &mb[kt * FKT + tid]);
        }
    };

    stage(0, 0);
    CP_ASYNC_COMMIT();

    char* Pp = smem + B_P + w * 32 * KVROW;

    for (int kt = 0; kt < FNT; kt++) {
        if (kt + 1 < FNT) {
            stage(kt + 1, (kt + 1) & 1);
            CP_ASYNC_COMMIT();
            CP_ASYNC_WAIT(1);
        } else {
            CP_ASYNC_WAIT(0);
        }
        __syncthreads();

        const int buf = kt & 1;
        const char* Kbuf = smem + B_K + buf * KBUF;
        const char* Vbuf = smem + B_V + buf * KBUF;
        const int* mk = (const int*)(smem + B_M + buf * (FKT * 4));

        // ---- S = Q @ K^T (32 x 64 per warp), 4 k16-steps ----
        float sc[2][8][4];
#pragma unroll
        for (int mi = 0; mi < 2; mi++)
#pragma unroll
            for (int j = 0; j < 8; j++)
#pragma unroll
                for (int c = 0; c < 4; c++) sc[mi][j][c] = 0.f;
#pragma unroll
        for (int s = 0; s < 4; s++) {
#pragma unroll
            for (int jn = 0; jn < 8; jn++) {
                uint32_t bf[2];
                const char* kr = Kbuf + (8 * jn + g) * KVROW + s * 32 + tig * 4;
                bf[0] = *(const uint32_t*)kr;
                bf[1] = *(const uint32_t*)(kr + 16);
                MMA_F16(sc[0][jn], aQ[0][s], bf);
                MMA_F16(sc[1][jn], aQ[1][s], bf);
            }
        }

        // ---- online softmax (log2 domain), per m-tile ----
#pragma unroll
        for (int mi = 0; mi < 2; mi++) {
#pragma unroll
            for (int jn = 0; jn < 8; jn++) {
                int2 mv = *(const int2*)&mk[8 * jn + 2 * tig];
                float ax = mv.x ? -1e30f : 0.f;
                float ay = mv.y ? -1e30f : 0.f;
                sc[mi][jn][0] = fmaf(sc[mi][jn][0], CS, ax);
                sc[mi][jn][1] = fmaf(sc[mi][jn][1], CS, ay);
                sc[mi][jn][2] = fmaf(sc[mi][jn][2], CS, ax);
                sc[mi][jn][3] = fmaf(sc[mi][jn][3], CS, ay);
            }
            float mx0 = -1e30f, mx1 = -1e30f;
#pragma unroll
            for (int jn = 0; jn < 8; jn++) {
                mx0 = fmaxf(mx0, fmaxf(sc[mi][jn][0], sc[mi][jn][1]));
                mx1 = fmaxf(mx1, fmaxf(sc[mi][jn][2], sc[mi][jn][3]));
            }
            mx0 = fmaxf(mx0, __shfl_xor_sync(0xFFFFFFFF, mx0, 1));
            mx0 = fmaxf(mx0, __shfl_xor_sync(0xFFFFFFFF, mx0, 2));
            mx1 = fmaxf(mx1, __shfl_xor_sync(0xFFFFFFFF, mx1, 1));
            mx1 = fmaxf(mx1, __shfl_xor_sync(0xFFFFFFFF, mx1, 2));

            const float nm0 = fmaxf(mrun[2 * mi], mx0);
            const float nm1 = fmaxf(mrun[2 * mi + 1], mx1);
            const float cor0 = fast_exp2(mrun[2 * mi] - nm0);
            const float cor1 = fast_exp2(mrun[2 * mi + 1] - nm1);
            mrun[2 * mi] = nm0;
            mrun[2 * mi + 1] = nm1;

            float s0 = 0.f, s1 = 0.f;
#pragma unroll
            for (int jn = 0; jn < 8; jn++) {
                sc[mi][jn][0] = fast_exp2(sc[mi][jn][0] - nm0);
                sc[mi][jn][1] = fast_exp2(sc[mi][jn][1] - nm0);
                sc[mi][jn][2] = fast_exp2(sc[mi][jn][2] - nm1);
                sc[mi][jn][3] = fast_exp2(sc[mi][jn][3] - nm1);
                s0 += sc[mi][jn][0] + sc[mi][jn][1];
                s1 += sc[mi][jn][2] + sc[mi][jn][3];
            }
            s0 += __shfl_xor_sync(0xFFFFFFFF, s0, 1);
            s0 += __shfl_xor_sync(0xFFFFFFFF, s0, 2);
            s1 += __shfl_xor_sync(0xFFFFFFFF, s1, 1);
            s1 += __shfl_xor_sync(0xFFFFFFFF, s1, 2);
            lrun[2 * mi] = lrun[2 * mi] * cor0 + s0;
            lrun[2 * mi + 1] = lrun[2 * mi + 1] * cor1 + s1;

#pragma unroll
            for (int j = 0; j < 8; j++) {
                oacc[mi][j][0] *= cor0;
                oacc[mi][j][1] *= cor0;
                oacc[mi][j][2] *= cor1;
                oacc[mi][j][3] *= cor1;
            }

            // P -> smem (fp16 half2 pairs)
#pragma unroll
            for (int jn = 0; jn < 8; jn++) {
                *(uint32_t*)(Pp + (16 * mi + g) * KVROW + jn * 16 + tig * 4) =
                    pack_h2(sc[mi][jn][0], sc[mi][jn][1]);
                *(uint32_t*)(Pp + (16 * mi + g + 8) * KVROW + jn * 16 + tig * 4) =
                    pack_h2(sc[mi][jn][2], sc[mi][jn][3]);
            }
        }
        __syncwarp();

        // ---- O += P @ V, 4 k16-steps ----
#pragma unroll
        for (int s2 = 0; s2 < 4; s2++) {
            uint32_t pa0[4], pa1[4];
            const int po = s2 * 32 + tig * 4;
            pa0[0] = *(const uint32_t*)(Pp + g * KVROW + po);
            pa0[1] = *(const uint32_t*)(Pp + (g + 8) * KVROW + po);
            pa0[2] = *(const uint32_t*)(Pp + g * KVROW + po + 16);
            pa0[3] = *(const uint32_t*)(Pp + (g + 8) * KVROW + po + 16);
            pa1[0] = *(const uint32_t*)(Pp + (g + 16) * KVROW + po);
            pa1[1] = *(const uint32_t*)(Pp + (g + 24) * KVROW + po);
            pa1[2] = *(const uint32_t*)(Pp + (g + 16) * KVROW + po + 16);
            pa1[3] = *(const uint32_t*)(Pp + (g + 24) * KVROW + po + 16);

            const int rb = s2 * 16 + tig * 2;
#pragma unroll
            for (int jn2 = 0; jn2 < 8; jn2++) {
                const int nb = (8 * jn2 + g) * 2;
                uint32_t x0 = *(const unsigned short*)(Vbuf + rb * KVROW + nb);
                uint32_t x1 = *(const unsigned short*)(Vbuf + (rb + 1) * KVROW + nb);
                uint32_t x2 = *(const unsigned short*)(Vbuf + (rb + 8) * KVROW + nb);
                uint32_t x3 = *(const unsigned short*)(Vbuf + (rb + 9) * KVROW + nb);
                uint32_t bfv[2];
                bfv[0] = x0 | (x1 << 16);
                bfv[1] = x2 | (x3 << 16);
                MMA_F16(oacc[0][jn2], pa0, bfv);
                MMA_F16(oacc[1][jn2], pa1, bfv);
            }
        }
        __syncthreads();
    }

    // ---- epilogue: normalize + store fp16 to g_A ----
#pragma unroll
    for (int mi = 0; mi < 2; mi++) {
        const float il0 = 1.f / lrun[2 * mi];
        const float il1 = 1.f / lrun[2 * mi + 1];
        __half* O0 = Out + ((size_t)(b * SEQ + qr0 + 16 * mi + g)) * DIM + h * HD;
        __half* O1 = Out + ((size_t)(b * SEQ + qr0 + 16 * mi + g + 8)) * DIM + h * HD;
#pragma unroll
        for (int jn2 = 0; jn2 < 8; jn2++) {
            *(uint32_t*)&O0[8 * jn2 + 2 * tig] =
                pack_h2(oacc[mi][jn2][0] * il0, oacc[mi][jn2][1] * il0);
            *(uint32_t*)&O1[8 * jn2 + 2 * tig] =
                pack_h2(oacc[mi][jn2][2] * il1, oacc[mi][jn2][3] * il1);
        }
    }
}

// ---------------------------------------------------------------------------
extern "C" void kernel_launch(void* const* d_in, const int* in_sizes, int n_in,
                              void* d_out, int out_size) {
    const float* q  = (const float*)d_in[0];
    const float* k  = (const float*)d_in[1];
    const float* v  = (const float*)d_in[2];
    const int* mask = (const int*)d_in[3];
    const float* Wq = (const float*)d_in[4];
    const float* bq = (const float*)d_in[5];
    const float* Wk = (const float*)d_in[6];
    const float* bk = (const float*)d_in[7];
    const float* Wv = (const float*)d_in[8];
    const float* bv = (const float*)d_in[9];
    const float* Wo = (const float*)d_in[10];
    const float* bo = (const float*)d_in[11];
    float* out = (float*)d_out;

    __half *pQ, *pK, *pV, *pA, *pWh, *pXh;
    cudaGetSymbolAddress((void**)&pQ, g_Q);
    cudaGetSymbolAddress((void**)&pK, g_K);
    cudaGetSymbolAddress((void**)&pV, g_V);
    cudaGetSymbolAddress((void**)&pA, g_A);
    cudaGetSymbolAddress((void**)&pWh, g_Wh);
    cudaGetSymbolAddress((void**)&pXh, g_Xh);

    cudaFuncSetAttribute(gemm_qkv, cudaFuncAttributeMaxDynamicSharedMemorySize, SM_GEMM_TOTAL);
    cudaFuncSetAttribute(gemm_out, cudaFuncAttributeMaxDynamicSharedMemorySize, SM_GEMM_TOTAL);
    cudaFuncSetAttribute(flash_attn_tc, cudaFuncAttributeMaxDynamicSharedMemorySize, FLASH_SMEM_BYTES);

    // --- fused fp32 -> fp16 pre-pass ---
    const int W8 = DIM * DIM / 8;       // 131072
    const int X8 = MROWS * DIM / 8;     // 524288
    ConvArgs ca;
    ca.src[0] = Wq; ca.dst[0] = pWh + 0 * (size_t)DIM * DIM; ca.n8[0] = W8;
    ca.src[1] = Wk; ca.dst[1] = pWh + 1 * (size_t)DIM * DIM; ca.n8[1] = W8;
    ca.src[2] = Wv; ca.dst[2] = pWh + 2 * (size_t)DIM * DIM; ca.n8[2] = W8;
    ca.src[3] = Wo; ca.dst[3] = pWh + 3 * (size_t)DIM * DIM; ca.n8[3] = W8;
    ca.src[4] = q;  ca.dst[4] = pXh + 0 * (size_t)MROWS * DIM; ca.n8[4] = X8;
    ca.src[5] = k;  ca.dst[5] = pXh + 1 * (size_t)MROWS * DIM; ca.n8[5] = X8;
    ca.src[6] = v;  ca.dst[6] = pXh + 2 * (size_t)MROWS * DIM; ca.n8[6] = X8;
    conv_f16_all<<<dim3(X8 / 1024, 7), 256>>>(ca);

    GemmArgs aq{pXh + 0 * (size_t)MROWS * DIM, pWh + 0 * (size_t)DIM * DIM, bq, pQ};
    GemmArgs ak{pXh + 1 * (size_t)MROWS * DIM, pWh + 1 * (size_t)DIM * DIM, bk, pK};
    GemmArgs av{pXh + 2 * (size_t)MROWS * DIM, pWh + 2 * (size_t)DIM * DIM, bv, pV};

    dim3 gqkv(DIM / GBN, MROWS / GBM, 3);   // (8, 32, 3) = 768 CTAs
    gemm_qkv<<<gqkv, 256, SM_GEMM_TOTAL>>>(aq, ak, av);

    flash_attn_tc<<<dim3(SEQ / 128, NH, BATCH), 128, FLASH_SMEM_BYTES>>>(mask, pA);

    dim3 go(DIM / GBN, MROWS / GBM);        // (8, 32) = 256 CTAs
    gemm_out<<<go, 256, SM_GEMM_TOTAL>>>(pA, pWh + 3 * (size_t)DIM * DIM, bo, out);
}

// round 11
// speedup vs baseline: 1.8093x; 1.0663x over previous
#include <cuda_runtime.h>
#include <cuda_fp16.h>
#include <cstdint>

// Problem constants
#define BATCH 2
#define SEQ   2048
#define DIM   1024
#define NH    16
#define HD    64
#define MROWS (BATCH * SEQ)   // 4096

// Scratch (allocation-free rule: __device__ globals)
__device__ __half g_Q[BATCH * NH * SEQ * HD];  // [b,h,s,hd] fp16
__device__ __half g_K[BATCH * NH * SEQ * HD];
__device__ __half g_V[BATCH * NH * SEQ * HD];
__device__ __half g_A[BATCH * SEQ * DIM];      // attn out [b,s,h*hd] fp16
__device__ __half g_Wh[4 * DIM * DIM];         // fp16 Wq,Wk,Wv,Wo
__device__ __half g_Xh[3 * (size_t)MROWS * DIM]; // fp16 q,k,v

// ---------------------------------------------------------------------------
// Helpers
// ---------------------------------------------------------------------------
__device__ __forceinline__ uint32_t smem_u32(const void* p) {
    uint32_t a;
    asm("{ .reg .u64 t; cvta.to.shared.u64 t, %1; cvt.u32.u64 %0, t; }" : "=r"(a) : "l"(p));
    return a;
}

#define CP_ASYNC16(dst, src) \
    asm volatile("cp.async.cg.shared.global [%0], [%1], 16;" :: "r"(dst), "l"(src))
#define CP_ASYNC4(dst, src) \
    asm volatile("cp.async.ca.shared.global [%0], [%1], 4;" :: "r"(dst), "l"(src))
#define CP_ASYNC_COMMIT() asm volatile("cp.async.commit_group;" ::: "memory")
#define CP_ASYNC_WAIT(n)  asm volatile("cp.async.wait_group %0;" :: "n"(n) : "memory")

// fp16 MMA, fp32 accumulate: m16n8k16
#define MMA_F16(d, av, bv)                                                    \
    asm volatile("mma.sync.aligned.m16n8k16.row.col.f32.f16.f16.f32 "         \
                 "{%0,%1,%2,%3}, {%4,%5,%6,%7}, {%8,%9}, {%0,%1,%2,%3};"      \
                 : "+f"((d)[0]), "+f"((d)[1]), "+f"((d)[2]), "+f"((d)[3])     \
                 : "r"((av)[0]), "r"((av)[1]), "r"((av)[2]), "r"((av)[3]),    \
                   "r"((bv)[0]), "r"((bv)[1]))

__device__ __forceinline__ uint32_t pack_h2(float a, float b) {
    __half2 h = __floats2half2_rn(a, b);
    return *(uint32_t*)&h;
}

// Fast exp2 on the FMA pipe. Rel err ~3e-6.
__device__ __forceinline__ float fast_exp2(float x) {
    x = fmaxf(x, -126.0f);
    float t = x + 12582912.0f;            // 2^23 + 2^22
    float i = t - 12582912.0f;
    float f = x - i;
    float p = 1.3333558e-3f;
    p = fmaf(p, f, 9.6181291e-3f);
    p = fmaf(p, f, 5.5504109e-2f);
    p = fmaf(p, f, 2.4022651e-1f);
    p = fmaf(p, f, 6.9314718e-1f);
    p = fmaf(p, f, 1.0f);
    int ib = __float_as_int(t) << 23;     // == i << 23 exactly
    return __int_as_float(__float_as_int(p) + ib);
}

// ---------------------------------------------------------------------------
// Fused fp32 -> fp16 conversion pre-pass (7 arrays, one launch).
// ---------------------------------------------------------------------------
struct ConvArgs {
    const float* src[7];
    __half* dst[7];
    int n8[7];     // number of 8-float groups
};

__global__ __launch_bounds__(256) void conv_f16_all(ConvArgs a) {
    const int seg = blockIdx.y;
    const float* src = a.src[seg];
    __half* dst = a.dst[seg];
    const int n8 = a.n8[seg];
    int i0 = blockIdx.x * 1024 + threadIdx.x;
    if (i0 >= n8) return;
#pragma unroll
    for (int t = 0; t < 4; t++) {
        int idx = i0 + t * 256;
        if (idx < n8) {
            float4 v0 = ((const float4*)src)[2 * idx];
            float4 v1 = ((const float4*)src)[2 * idx + 1];
            uint4 o;
            o.x = pack_h2(v0.x, v0.y);
            o.y = pack_h2(v0.z, v0.w);
            o.z = pack_h2(v1.x, v1.y);
            o.w = pack_h2(v1.z, v1.w);
            ((uint4*)dst)[idx] = o;
        }
    }
}

// ---------------------------------------------------------------------------
// fp16 mma.sync GEMM (unchanged from R10, proven): C = A @ W^T + bias.
// CTA tile 128x128, BK=64, 256 threads = 8 warps (4m x 2n), 32x64. 2 CTAs/SM.
// ---------------------------------------------------------------------------
#define GBM 128
#define GBN 128
#define GBK 64
#define NKT (DIM / GBK)                 // 16
#define SA_BYTES (GBM * GBK * 2)        // 16384
#define SB_BYTES (GBN * GBK * 2)        // 16384
#define SM_GEMM_TOTAL (2 * (SA_BYTES + SB_BYTES))   // 65536

struct GemmArgs {
    const __half* A;
    const __half* W;
    const float* bias;
    void* C;
};

__device__ __forceinline__ uint32_t lds32_sw(const char* base, int row, int chunk, int off) {
    return *(const uint32_t*)(base + row * 128 + (((chunk) ^ (row & 7)) << 4) + off);
}

template <int SPLIT_HEADS>
__device__ __forceinline__ void gemm_body(const __half* __restrict__ A,
                                          const __half* __restrict__ W,
                                          const float* __restrict__ bias,
                                          void* __restrict__ Cv) {
    extern __shared__ char smem[];
    const char* sAc = smem;
    const char* sBc = smem + 2 * SA_BYTES;
    const uint32_t sA = smem_u32(smem);
    const uint32_t sB = sA + 2 * SA_BYTES;

    const int tid = threadIdx.x;
    const int lane = tid & 31;
    const int wid = tid >> 5;      // 0..7
    const int wm = wid & 3;        // 0..3 (m: 4 x 32)
    const int wn = wid >> 2;       // 0..1 (n: 2 x 64)
    const int g = lane >> 2;
    const int tig = lane & 3;
    const int m0 = blockIdx.y * GBM;
    const int n0 = blockIdx.x * GBN;

    float acc[2][8][4];
#pragma unroll
    for (int i = 0; i < 2; i++)
#pragma unroll
        for (int j = 0; j < 8; j++)
#pragma unroll
            for (int c = 0; c < 4; c++) acc[i][j][c] = 0.f;

    auto stage = [&](int kt, int buf) {
        const int k0 = kt * GBK;    // halves
#pragma unroll
        for (int t = 0; t < 4; t++) {
            int idx = tid + t * 256;
            int row = idx >> 3;
            int c = idx & 7;
            uint32_t dst = sA + buf * SA_BYTES + row * 128 + ((c ^ (row & 7)) << 4);
            CP_ASYNC16(dst, &A[(size_t)(m0 + row) * DIM + k0 + c * 8]);
        }
#pragma unroll
        for (int t = 0; t < 4; t++) {
            int idx = tid + t * 256;
            int row = idx >> 3;
            int c = idx & 7;
            uint32_t dst = sB + buf * SB_BYTES + row * 128 + ((c ^ (row & 7)) << 4);
            CP_ASYNC16(dst, &W[(size_t)(n0 + row) * DIM + k0 + c * 8]);
        }
    };

    stage(0, 0);
    CP_ASYNC_COMMIT();

    for (int kt = 0; kt < NKT; kt++) {
        if (kt + 1 < NKT) {
            stage(kt + 1, (kt + 1) & 1);
            CP_ASYNC_COMMIT();
            CP_ASYNC_WAIT(1);
        } else {
            CP_ASYNC_WAIT(0);
        }
        __syncthreads();

        const char* Ab = sAc + (kt & 1) * SA_BYTES;
        const char* Bb = sBc + (kt & 1) * SB_BYTES;
#pragma unroll
        for (int s = 0; s < 4; s++) {
            const int c0 = 2 * s;
            const int off = tig * 4;
            uint32_t a[2][4];
#pragma unroll
            for (int i = 0; i < 2; i++) {
                int r1 = wm * 32 + i * 16 + g;
                int r2 = r1 + 8;
                a[i][0] = lds32_sw(Ab, r1, c0, off);
                a[i][1] = lds32_sw(Ab, r2, c0, off);
                a[i][2] = lds32_sw(Ab, r1, c0 + 1, off);
                a[i][3] = lds32_sw(Ab, r2, c0 + 1, off);
            }
            uint32_t bf[8][2];
#pragma unroll
            for (int j = 0; j < 8; j++) {
                int rn = wn * 64 + j * 8 + g;
                bf[j][0] = lds32_sw(Bb, rn, c0, off);
                bf[j][1] = lds32_sw(Bb, rn, c0 + 1, off);
            }
#pragma unroll
            for (int i = 0; i < 2; i++)
#pragma unroll
                for (int j = 0; j < 8; j++) MMA_F16(acc[i][j], a[i], bf[j]);
        }
        __syncthreads();
    }

#pragma unroll
    for (int i = 0; i < 2; i++) {
        const int m1 = m0 + wm * 32 + i * 16 + g;
        const int m2 = m1 + 8;
#pragma unroll
        for (int j = 0; j < 8; j++) {
            const int n = n0 + wn * 64 + j * 8 + tig * 2;
            const float2 bb = *(const float2*)&bias[n];
            if (SPLIT_HEADS) {
                __half* C = (__half*)Cv;
                uint32_t h1 = pack_h2(acc[i][j][0] + bb.x, acc[i][j][1] + bb.y);
                uint32_t h2 = pack_h2(acc[i][j][2] + bb.x, acc[i][j][3] + bb.y);
                int h = n >> 6;
                int hd = n & (HD - 1);
                {
                    int b = m1 >> 11, sq = m1 & (SEQ - 1);
                    *(uint32_t*)&C[((size_t)((b * NH + h) * SEQ + sq)) * HD + hd] = h1;
                }
                {
                    int b = m2 >> 11, sq = m2 & (SEQ - 1);
                    *(uint32_t*)&C[((size_t)((b * NH + h) * SEQ + sq)) * HD + hd] = h2;
                }
            } else {
                float* C = (float*)Cv;
                float2 r1, r2;
                r1.x = acc[i][j][0] + bb.x;
                r1.y = acc[i][j][1] + bb.y;
                r2.x = acc[i][j][2] + bb.x;
                r2.y = acc[i][j][3] + bb.y;
                *(float2*)&C[(size_t)m1 * DIM + n] = r1;
                *(float2*)&C[(size_t)m2 * DIM + n] = r2;
            }
        }
    }
}

__global__ __launch_bounds__(256, 2) void gemm_qkv(GemmArgs a0, GemmArgs a1, GemmArgs a2) {
    const GemmArgs& a = (blockIdx.z == 0) ? a0 : (blockIdx.z == 1) ? a1 : a2;
    gemm_body<1>(a.A, a.W, a.bias, a.C);
}

__global__ __launch_bounds__(256, 2) void gemm_out(const __half* __restrict__ A,
                                                   const __half* __restrict__ W,
                                                   const float* __restrict__ bias,
                                                   float* __restrict__ C) {
    gemm_body<0>(A, W, bias, C);
}

// ---------------------------------------------------------------------------
// fp16 tensor-core flash attention with REGISTER-PASSED P (no smem P).
// S C-fragments feed PV A-fragments directly: for k-chunk s2, the A-frag is
// {pack(sc[2s2][0..1]), pack(sc[2s2][2..3]), pack(sc[2s2+1][0..1]),
//  pack(sc[2s2+1][2..3])} -- identical layout by m16n8k16 definition.
// 128 thr (4 warps), 128 q-rows/CTA, M=32/warp. KV 64-row tiles, cp.async
// double-buffered. smem 37.4KB.
// ---------------------------------------------------------------------------
#define FKT 64
#define FNT (SEQ / FKT)   // 32
#define KVROW 144         // bytes per KV row (64 halves + 8 pad)
#define KBUF (FKT * KVROW)        // 9216
#define B_K 0
#define B_V (2 * KBUF)            // 18432
#define B_M (4 * KBUF)            // 36864 (mask region)
#define FLASH_SMEM_BYTES (B_M + 2 * FKT * 4)  // 37376

#define CS 0.18033688f  // 0.125 * log2(e)

__global__ __launch_bounds__(128) void flash_attn_tc(const int* __restrict__ mask,
                                                     __half* __restrict__ Out) {
    extern __shared__ char smem[];
    const uint32_t sbase = smem_u32(smem);

    const int b = blockIdx.z;
    const int h = blockIdx.y;
    const int tid = threadIdx.x;
    const int w = tid >> 5;
    const int lane = tid & 31;
    const int g = lane >> 2;
    const int tig = lane & 3;
    const int qr0 = blockIdx.x * 128 + w * 32;

    const __half* Qp = g_Q + ((size_t)((b * NH + h) * SEQ) + qr0) * HD;
    const __half* Kb = g_K + ((size_t)((b * NH + h) * SEQ)) * HD;
    const __half* Vb = g_V + ((size_t)((b * NH + h) * SEQ)) * HD;
    const int* mb = mask + b * SEQ;

    // Persistent Q A-fragments (fp16, half2-packed)
    uint32_t aQ[2][4][4];
#pragma unroll
    for (int mi = 0; mi < 2; mi++) {
        const __half* Qm = Qp + (size_t)(16 * mi) * HD;
#pragma unroll
        for (int s = 0; s < 4; s++) {
            aQ[mi][s][0] = *(const uint32_t*)&Qm[g * HD + s * 16 + tig * 2];
            aQ[mi][s][1] = *(const uint32_t*)&Qm[(g + 8) * HD + s * 16 + tig * 2];
            aQ[mi][s][2] = *(const uint32_t*)&Qm[g * HD + s * 16 + 8 + tig * 2];
            aQ[mi][s][3] = *(const uint32_t*)&Qm[(g + 8) * HD + s * 16 + 8 + tig * 2];
        }
    }

    float oacc[2][8][4];
#pragma unroll
    for (int mi = 0; mi < 2; mi++)
#pragma unroll
        for (int j = 0; j < 8; j++)
#pragma unroll
            for (int c = 0; c < 4; c++) oacc[mi][j][c] = 0.f;
    float mrun[4] = {-1e30f, -1e30f, -1e30f, -1e30f};
    float lrun[4] = {0.f, 0.f, 0.f, 0.f};

    auto stage = [&](int kt, int buf) {
        const __half* Kg = Kb + (size_t)kt * FKT * HD;
        const __half* Vg = Vb + (size_t)kt * FKT * HD;
        const uint32_t dK = sbase + B_K + buf * KBUF;
        const uint32_t dV = sbase + B_V + buf * KBUF;
#pragma unroll
        for (int t = 0; t < 4; t++) {
            int idx = tid + t * 128;       // 0..511
            int row = idx >> 3;            // 0..63
            int c = idx & 7;               // 16B chunk
            CP_ASYNC16(dK + row * KVROW + c * 16, &Kg[row * HD + c * 8]);
            CP_ASYNC16(dV + row * KVROW + c * 16, &Vg[row * HD + c * 8]);
        }
        if (tid < FKT) {
            CP_ASYNC4(sbase + B_M + buf * (FKT * 4) + tid * 4, &mb[kt * FKT + tid]);
        }
    };

    stage(0, 0);
    CP_ASYNC_COMMIT();

    for (int kt = 0; kt < FNT; kt++) {
        if (kt + 1 < FNT) {
            stage(kt + 1, (kt + 1) & 1);
            CP_ASYNC_COMMIT();
            CP_ASYNC_WAIT(1);
        } else {
            CP_ASYNC_WAIT(0);
        }
        __syncthreads();

        const int buf = kt & 1;
        const char* Kbuf = smem + B_K + buf * KBUF;
        const char* Vbuf = smem + B_V + buf * KBUF;
        const int* mk = (const int*)(smem + B_M + buf * (FKT * 4));

        // ---- S = Q @ K^T (32 x 64 per warp), 4 k16-steps ----
        float sc[2][8][4];
#pragma unroll
        for (int mi = 0; mi < 2; mi++)
#pragma unroll
            for (int j = 0; j < 8; j++)
#pragma unroll
                for (int c = 0; c < 4; c++) sc[mi][j][c] = 0.f;
#pragma unroll
        for (int s = 0; s < 4; s++) {
#pragma unroll
            for (int jn = 0; jn < 8; jn++) {
                uint32_t bf[2];
                const char* kr = Kbuf + (8 * jn + g) * KVROW + s * 32 + tig * 4;
                bf[0] = *(const uint32_t*)kr;
                bf[1] = *(const uint32_t*)(kr + 16);
                MMA_F16(sc[0][jn], aQ[0][s], bf);
                MMA_F16(sc[1][jn], aQ[1][s], bf);
            }
        }

        // ---- online softmax (log2 domain), per m-tile ----
#pragma unroll
        for (int mi = 0; mi < 2; mi++) {
#pragma unroll
            for (int jn = 0; jn < 8; jn++) {
                int2 mv = *(const int2*)&mk[8 * jn + 2 * tig];
                float ax = mv.x ? -1e30f : 0.f;
                float ay = mv.y ? -1e30f : 0.f;
                sc[mi][jn][0] = fmaf(sc[mi][jn][0], CS, ax);
                sc[mi][jn][1] = fmaf(sc[mi][jn][1], CS, ay);
                sc[mi][jn][2] = fmaf(sc[mi][jn][2], CS, ax);
                sc[mi][jn][3] = fmaf(sc[mi][jn][3], CS, ay);
            }
            float mx0 = -1e30f, mx1 = -1e30f;
#pragma unroll
            for (int jn = 0; jn < 8; jn++) {
                mx0 = fmaxf(mx0, fmaxf(sc[mi][jn][0], sc[mi][jn][1]));
                mx1 = fmaxf(mx1, fmaxf(sc[mi][jn][2], sc[mi][jn][3]));
            }
            mx0 = fmaxf(mx0, __shfl_xor_sync(0xFFFFFFFF, mx0, 1));
            mx0 = fmaxf(mx0, __shfl_xor_sync(0xFFFFFFFF, mx0, 2));
            mx1 = fmaxf(mx1, __shfl_xor_sync(0xFFFFFFFF, mx1, 1));
            mx1 = fmaxf(mx1, __shfl_xor_sync(0xFFFFFFFF, mx1, 2));

            const float nm0 = fmaxf(mrun[2 * mi], mx0);
            const float nm1 = fmaxf(mrun[2 * mi + 1], mx1);
            const float cor0 = fast_exp2(mrun[2 * mi] - nm0);
            const float cor1 = fast_exp2(mrun[2 * mi + 1] - nm1);
            mrun[2 * mi] = nm0;
            mrun[2 * mi + 1] = nm1;

            float s0 = 0.f, s1 = 0.f;
#pragma unroll
            for (int jn = 0; jn < 8; jn++) {
                sc[mi][jn][0] = fast_exp2(sc[mi][jn][0] - nm0);
                sc[mi][jn][1] = fast_exp2(sc[mi][jn][1] - nm0);
                sc[mi][jn][2] = fast_exp2(sc[mi][jn][2] - nm1);
                sc[mi][jn][3] = fast_exp2(sc[mi][jn][3] - nm1);
                s0 += sc[mi][jn][0] + sc[mi][jn][1];
                s1 += sc[mi][jn][2] + sc[mi][jn][3];
            }
            s0 += __shfl_xor_sync(0xFFFFFFFF, s0, 1);
            s0 += __shfl_xor_sync(0xFFFFFFFF, s0, 2);
            s1 += __shfl_xor_sync(0xFFFFFFFF, s1, 1);
            s1 += __shfl_xor_sync(0xFFFFFFFF, s1, 2);
            lrun[2 * mi] = lrun[2 * mi] * cor0 + s0;
            lrun[2 * mi + 1] = lrun[2 * mi + 1] * cor1 + s1;

#pragma unroll
            for (int j = 0; j < 8; j++) {
                oacc[mi][j][0] *= cor0;
                oacc[mi][j][1] *= cor0;
                oacc[mi][j][2] *= cor1;
                oacc[mi][j][3] *= cor1;
            }
        }

        // ---- O += P @ V, P fragments built directly from sc registers ----
#pragma unroll
        for (int s2 = 0; s2 < 4; s2++) {
            uint32_t pa0[4], pa1[4];
            pa0[0] = pack_h2(sc[0][2 * s2][0],     sc[0][2 * s2][1]);
            pa0[1] = pack_h2(sc[0][2 * s2][2],     sc[0][2 * s2][3]);
            pa0[2] = pack_h2(sc[0][2 * s2 + 1][0], sc[0][2 * s2 + 1][1]);
            pa0[3] = pack_h2(sc[0][2 * s2 + 1][2], sc[0][2 * s2 + 1][3]);
            pa1[0] = pack_h2(sc[1][2 * s2][0],     sc[1][2 * s2][1]);
            pa1[1] = pack_h2(sc[1][2 * s2][2],     sc[1][2 * s2][3]);
            pa1[2] = pack_h2(sc[1][2 * s2 + 1][0], sc[1][2 * s2 + 1][1]);
            pa1[3] = pack_h2(sc[1][2 * s2 + 1][2], sc[1][2 * s2 + 1][3]);

            const int rb = s2 * 16 + tig * 2;
#pragma unroll
            for (int jn2 = 0; jn2 < 8; jn2++) {
                const int nb = (8 * jn2 + g) * 2;
                uint32_t x0 = *(const unsigned short*)(Vbuf + rb * KVROW + nb);
                uint32_t x1 = *(const unsigned short*)(Vbuf + (rb + 1) * KVROW + nb);
                uint32_t x2 = *(const unsigned short*)(Vbuf + (rb + 8) * KVROW + nb);
                uint32_t x3 = *(const unsigned short*)(Vbuf + (rb + 9) * KVROW + nb);
                uint32_t bfv[2];
                bfv[0] = x0 | (x1 << 16);
                bfv[1] = x2 | (x3 << 16);
                MMA_F16(oacc[0][jn2], pa0, bfv);
                MMA_F16(oacc[1][jn2], pa1, bfv);
            }
        }
        __syncthreads();
    }

    // ---- epilogue: normalize + store fp16 to g_A ----
#pragma unroll
    for (int mi = 0; mi < 2; mi++) {
        const float il0 = 1.f / lrun[2 * mi];
        const float il1 = 1.f / lrun[2 * mi + 1];
        __half* O0 = Out + ((size_t)(b * SEQ + qr0 + 16 * mi + g)) * DIM + h * HD;
        __half* O1 = Out + ((size_t)(b * SEQ + qr0 + 16 * mi + g + 8)) * DIM + h * HD;
#pragma unroll
        for (int jn2 = 0; jn2 < 8; jn2++) {
            *(uint32_t*)&O0[8 * jn2 + 2 * tig] =
                pack_h2(oacc[mi][jn2][0] * il0, oacc[mi][jn2][1] * il0);
            *(uint32_t*)&O1[8 * jn2 + 2 * tig] =
                pack_h2(oacc[mi][jn2][2] * il1, oacc[mi][jn2][3] * il1);
        }
    }
}

// ---------------------------------------------------------------------------
extern "C" void kernel_launch(void* const* d_in, const int* in_sizes, int n_in,
                              void* d_out, int out_size) {
    const float* q  = (const float*)d_in[0];
    const float* k  = (const float*)d_in[1];
    const float* v  = (const float*)d_in[2];
    const int* mask = (const int*)d_in[3];
    const float* Wq = (const float*)d_in[4];
    const float* bq = (const float*)d_in[5];
    const float* Wk = (const float*)d_in[6];
    const float* bk = (const float*)d_in[7];
    const float* Wv = (const float*)d_in[8];
    const float* bv = (const float*)d_in[9];
    const float* Wo = (const float*)d_in[10];
    const float* bo = (const float*)d_in[11];
    float* out = (float*)d_out;

    __half *pQ, *pK, *pV, *pA, *pWh, *pXh;
    cudaGetSymbolAddress((void**)&pQ, g_Q);
    cudaGetSymbolAddress((void**)&pK, g_K);
    cudaGetSymbolAddress((void**)&pV, g_V);
    cudaGetSymbolAddress((void**)&pA, g_A);
    cudaGetSymbolAddress((void**)&pWh, g_Wh);
    cudaGetSymbolAddress((void**)&pXh, g_Xh);

    cudaFuncSetAttribute(gemm_qkv, cudaFuncAttributeMaxDynamicSharedMemorySize, SM_GEMM_TOTAL);
    cudaFuncSetAttribute(gemm_out, cudaFuncAttributeMaxDynamicSharedMemorySize, SM_GEMM_TOTAL);
    cudaFuncSetAttribute(flash_attn_tc, cudaFuncAttributeMaxDynamicSharedMemorySize, FLASH_SMEM_BYTES);

    // --- fused fp32 -> fp16 pre-pass ---
    const int W8 = DIM * DIM / 8;       // 131072
    const int X8 = MROWS * DIM / 8;     // 524288
    ConvArgs ca;
    ca.src[0] = Wq; ca.dst[0] = pWh + 0 * (size_t)DIM * DIM; ca.n8[0] = W8;
    ca.src[1] = Wk; ca.dst[1] = pWh + 1 * (size_t)DIM * DIM; ca.n8[1] = W8;
    ca.src[2] = Wv; ca.dst[2] = pWh + 2 * (size_t)DIM * DIM; ca.n8[2] = W8;
    ca.src[3] = Wo; ca.dst[3] = pWh + 3 * (size_t)DIM * DIM; ca.n8[3] = W8;
    ca.src[4] = q;  ca.dst[4] = pXh + 0 * (size_t)MROWS * DIM; ca.n8[4] = X8;
    ca.src[5] = k;  ca.dst[5] = pXh + 1 * (size_t)MROWS * DIM; ca.n8[5] = X8;
    ca.src[6] = v;  ca.dst[6] = pXh + 2 * (size_t)MROWS * DIM; ca.n8[6] = X8;
    conv_f16_all<<<dim3(X8 / 1024, 7), 256>>>(ca);

    GemmArgs aq{pXh + 0 * (size_t)MROWS * DIM, pWh + 0 * (size_t)DIM * DIM, bq, pQ};
    GemmArgs ak{pXh + 1 * (size_t)MROWS * DIM, pWh + 1 * (size_t)DIM * DIM, bk, pK};
    GemmArgs av{pXh + 2 * (size_t)MROWS * DIM, pWh + 2 * (size_t)DIM * DIM, bv, pV};

    dim3 gqkv(DIM / GBN, MROWS / GBM, 3);   // (8, 32, 3) = 768 CTAs
    gemm_qkv<<<gqkv, 256, SM_GEMM_TOTAL>>>(aq, ak, av);

    flash_attn_tc<<<dim3(SEQ / 128, NH, BATCH), 128, FLASH_SMEM_BYTES>>>(mask, pA);

    dim3 go(DIM / GBN, MROWS / GBM);        // (8, 32) = 256 CTAs
    gemm_out<<<go, 256, SM_GEMM_TOTAL>>>(pA, pWh + 3 * (size_t)DIM * DIM, bo, out);
}

// round 12
// speedup vs baseline: 1.9556x; 1.0809x over previous
#include <cuda_runtime.h>
#include <cuda_fp16.h>
#include <cstdint>

// Problem constants
#define BATCH 2
#define SEQ   2048
#define DIM   1024
#define NH    16
#define HD    64
#define MROWS (BATCH * SEQ)   // 4096

// Scratch (allocation-free rule: __device__ globals)
__device__ __half g_Q[BATCH * NH * SEQ * HD];  // [b,h,s,hd] fp16
__device__ __half g_K[BATCH * NH * SEQ * HD];
__device__ __half g_V[BATCH * NH * SEQ * HD];
__device__ __half g_A[BATCH * SEQ * DIM];      // attn out [b,s,h*hd] fp16
__device__ __half g_Wh[4 * DIM * DIM];         // fp16 Wq,Wk,Wv,Wo
__device__ __half g_Xh[3 * (size_t)MROWS * DIM]; // fp16 q,k,v

// ---------------------------------------------------------------------------
// Helpers
// ---------------------------------------------------------------------------
__device__ __forceinline__ uint32_t smem_u32(const void* p) {
    uint32_t a;
    asm("{ .reg .u64 t; cvta.to.shared.u64 t, %1; cvt.u32.u64 %0, t; }" : "=r"(a) : "l"(p));
    return a;
}

#define CP_ASYNC16(dst, src) \
    asm volatile("cp.async.cg.shared.global [%0], [%1], 16;" :: "r"(dst), "l"(src))
#define CP_ASYNC4(dst, src) \
    asm volatile("cp.async.ca.shared.global [%0], [%1], 4;" :: "r"(dst), "l"(src))
#define CP_ASYNC_COMMIT() asm volatile("cp.async.commit_group;" ::: "memory")
#define CP_ASYNC_WAIT(n)  asm volatile("cp.async.wait_group %0;" :: "n"(n) : "memory")

// fp16 MMA, fp32 accumulate: m16n8k16
#define MMA_F16(d, av, bv)                                                    \
    asm volatile("mma.sync.aligned.m16n8k16.row.col.f32.f16.f16.f32 "         \
                 "{%0,%1,%2,%3}, {%4,%5,%6,%7}, {%8,%9}, {%0,%1,%2,%3};"      \
                 : "+f"((d)[0]), "+f"((d)[1]), "+f"((d)[2]), "+f"((d)[3])     \
                 : "r"((av)[0]), "r"((av)[1]), "r"((av)[2]), "r"((av)[3]),    \
                   "r"((bv)[0]), "r"((bv)[1]))

#define LDSM_X4(r0, r1, r2, r3, addr)                                         \
    asm volatile("ldmatrix.sync.aligned.m8n8.x4.shared.b16 {%0,%1,%2,%3}, [%4];" \
                 : "=r"(r0), "=r"(r1), "=r"(r2), "=r"(r3) : "r"(addr))

#define LDSM_X4_T(r0, r1, r2, r3, addr)                                       \
    asm volatile("ldmatrix.sync.aligned.m8n8.x4.trans.shared.b16 {%0,%1,%2,%3}, [%4];" \
                 : "=r"(r0), "=r"(r1), "=r"(r2), "=r"(r3) : "r"(addr))

__device__ __forceinline__ uint32_t pack_h2(float a, float b) {
    __half2 h = __floats2half2_rn(a, b);
    return *(uint32_t*)&h;
}

// Fast exp2 on the FMA pipe. Rel err ~3e-6.
__device__ __forceinline__ float fast_exp2(float x) {
    x = fmaxf(x, -126.0f);
    float t = x + 12582912.0f;            // 2^23 + 2^22
    float i = t - 12582912.0f;
    float f = x - i;
    float p = 1.3333558e-3f;
    p = fmaf(p, f, 9.6181291e-3f);
    p = fmaf(p, f, 5.5504109e-2f);
    p = fmaf(p, f, 2.4022651e-1f);
    p = fmaf(p, f, 6.9314718e-1f);
    p = fmaf(p, f, 1.0f);
    int ib = __float_as_int(t) << 23;     // == i << 23 exactly
    return __int_as_float(__float_as_int(p) + ib);
}

// ---------------------------------------------------------------------------
// Fused fp32 -> fp16 conversion pre-pass (7 arrays, one launch).
// ---------------------------------------------------------------------------
struct ConvArgs {
    const float* src[7];
    __half* dst[7];
    int n8[7];     // number of 8-float groups
};

__global__ __launch_bounds__(256) void conv_f16_all(ConvArgs a) {
    const int seg = blockIdx.y;
    const float* src = a.src[seg];
    __half* dst = a.dst[seg];
    const int n8 = a.n8[seg];
    int i0 = blockIdx.x * 1024 + threadIdx.x;
    if (i0 >= n8) return;
#pragma unroll
    for (int t = 0; t < 4; t++) {
        int idx = i0 + t * 256;
        if (idx < n8) {
            float4 v0 = ((const float4*)src)[2 * idx];
            float4 v1 = ((const float4*)src)[2 * idx + 1];
            uint4 o;
            o.x = pack_h2(v0.x, v0.y);
            o.y = pack_h2(v0.z, v0.w);
            o.z = pack_h2(v1.x, v1.y);
            o.w = pack_h2(v1.z, v1.w);
            ((uint4*)dst)[idx] = o;
        }
    }
}

// ---------------------------------------------------------------------------
// fp16 mma.sync GEMM with ldmatrix fragment loads: C = A @ W^T + bias.
// CTA tile 128x128, BK=64, 256 threads = 8 warps (4m x 2n), 32x64. 2 CTAs/SM.
// ---------------------------------------------------------------------------
#define GBM 128
#define GBN 128
#define GBK 64
#define NKT (DIM / GBK)                 // 16
#define SA_BYTES (GBM * GBK * 2)        // 16384
#define SB_BYTES (GBN * GBK * 2)        // 16384
#define SM_GEMM_TOTAL (2 * (SA_BYTES + SB_BYTES))   // 65536

struct GemmArgs {
    const __half* A;
    const __half* W;
    const float* bias;
    void* C;
};

template <int SPLIT_HEADS>
__device__ __forceinline__ void gemm_body(const __half* __restrict__ A,
                                          const __half* __restrict__ W,
                                          const float* __restrict__ bias,
                                          void* __restrict__ Cv) {
    extern __shared__ char smem[];
    const uint32_t sA = smem_u32(smem);
    const uint32_t sB = sA + 2 * SA_BYTES;

    const int tid = threadIdx.x;
    const int lane = tid & 31;
    const int wid = tid >> 5;      // 0..7
    const int wm = wid & 3;        // 0..3 (m: 4 x 32)
    const int wn = wid >> 2;       // 0..1 (n: 2 x 64)
    const int g = lane >> 2;
    const int tig = lane & 3;
    const int m0 = blockIdx.y * GBM;
    const int n0 = blockIdx.x * GBN;

    // ldmatrix lane decomposition
    const int jL = lane >> 3;      // matrix index 0..3
    const int iL = lane & 7;       // row within matrix
    // A x4: matrix j -> (m_off = (j&1)*8, chunk_off = j>>1)
    const int rA0 = wm * 32 + (jL & 1) * 8 + iL;
    const int rA1 = rA0 + 16;
    const int cA = jL >> 1;
    // B x4: matrix j -> (n_off = (j>>1)*8, chunk_off = j&1)
    const int cB = jL & 1;
    int rB[4];
#pragma unroll
    for (int bg = 0; bg < 4; bg++) rB[bg] = wn * 64 + bg * 16 + (jL >> 1) * 8 + iL;

    float acc[2][8][4];
#pragma unroll
    for (int i = 0; i < 2; i++)
#pragma unroll
        for (int j = 0; j < 8; j++)
#pragma unroll
            for (int c = 0; c < 4; c++) acc[i][j][c] = 0.f;

    auto stage = [&](int kt, int buf) {
        const int k0 = kt * GBK;    // halves
#pragma unroll
        for (int t = 0; t < 4; t++) {
            int idx = tid + t * 256;
            int row = idx >> 3;
            int c = idx & 7;
            uint32_t dst = sA + buf * SA_BYTES + row * 128 + ((c ^ (row & 7)) << 4);
            CP_ASYNC16(dst, &A[(size_t)(m0 + row) * DIM + k0 + c * 8]);
        }
#pragma unroll
        for (int t = 0; t < 4; t++) {
            int idx = tid + t * 256;
            int row = idx >> 3;
            int c = idx & 7;
            uint32_t dst = sB + buf * SB_BYTES + row * 128 + ((c ^ (row & 7)) << 4);
            CP_ASYNC16(dst, &W[(size_t)(n0 + row) * DIM + k0 + c * 8]);
        }
    };

    stage(0, 0);
    CP_ASYNC_COMMIT();

    for (int kt = 0; kt < NKT; kt++) {
        if (kt + 1 < NKT) {
            stage(kt + 1, (kt + 1) & 1);
            CP_ASYNC_COMMIT();
            CP_ASYNC_WAIT(1);
        } else {
            CP_ASYNC_WAIT(0);
        }
        __syncthreads();

        const uint32_t abuf = sA + (kt & 1) * SA_BYTES;
        const uint32_t bbuf = sB + (kt & 1) * SB_BYTES;
#pragma unroll
        for (int s = 0; s < 4; s++) {
            uint32_t a[2][4];
            {
                int ch = 2 * s + cA;
                uint32_t ad0 = abuf + rA0 * 128 + ((ch ^ (rA0 & 7)) << 4);
                uint32_t ad1 = abuf + rA1 * 128 + ((ch ^ (rA1 & 7)) << 4);
                LDSM_X4(a[0][0], a[0][1], a[0][2], a[0][3], ad0);
                LDSM_X4(a[1][0], a[1][1], a[1][2], a[1][3], ad1);
            }
            uint32_t bf[8][2];
            {
                int ch = 2 * s + cB;
#pragma unroll
                for (int bg = 0; bg < 4; bg++) {
                    uint32_t ad = bbuf + rB[bg] * 128 + ((ch ^ (rB[bg] & 7)) << 4);
                    LDSM_X4(bf[2 * bg][0], bf[2 * bg][1],
                            bf[2 * bg + 1][0], bf[2 * bg + 1][1], ad);
                }
            }
#pragma unroll
            for (int i = 0; i < 2; i++)
#pragma unroll
                for (int j = 0; j < 8; j++) MMA_F16(acc[i][j], a[i], bf[j]);
        }
        __syncthreads();
    }

#pragma unroll
    for (int i = 0; i < 2; i++) {
        const int m1 = m0 + wm * 32 + i * 16 + g;
        const int m2 = m1 + 8;
#pragma unroll
        for (int j = 0; j < 8; j++) {
            const int n = n0 + wn * 64 + j * 8 + tig * 2;
            const float2 bb = *(const float2*)&bias[n];
            if (SPLIT_HEADS) {
                __half* C = (__half*)Cv;
                uint32_t h1 = pack_h2(acc[i][j][0] + bb.x, acc[i][j][1] + bb.y);
                uint32_t h2 = pack_h2(acc[i][j][2] + bb.x, acc[i][j][3] + bb.y);
                int h = n >> 6;
                int hd = n & (HD - 1);
                {
                    int b = m1 >> 11, sq = m1 & (SEQ - 1);
                    *(uint32_t*)&C[((size_t)((b * NH + h) * SEQ + sq)) * HD + hd] = h1;
                }
                {
                    int b = m2 >> 11, sq = m2 & (SEQ - 1);
                    *(uint32_t*)&C[((size_t)((b * NH + h) * SEQ + sq)) * HD + hd] = h2;
                }
            } else {
                float* C = (float*)Cv;
                float2 r1, r2;
                r1.x = acc[i][j][0] + bb.x;
                r1.y = acc[i][j][1] + bb.y;
                r2.x = acc[i][j][2] + bb.x;
                r2.y = acc[i][j][3] + bb.y;
                *(float2*)&C[(size_t)m1 * DIM + n] = r1;
                *(float2*)&C[(size_t)m2 * DIM + n] = r2;
            }
        }
    }
}

__global__ __launch_bounds__(256, 2) void gemm_qkv(GemmArgs a0, GemmArgs a1, GemmArgs a2) {
    const GemmArgs& a = (blockIdx.z == 0) ? a0 : (blockIdx.z == 1) ? a1 : a2;
    gemm_body<1>(a.A, a.W, a.bias, a.C);
}

__global__ __launch_bounds__(256, 2) void gemm_out(const __half* __restrict__ A,
                                                   const __half* __restrict__ W,
                                                   const float* __restrict__ bias,
                                                   float* __restrict__ C) {
    gemm_body<0>(A, W, bias, C);
}

// ---------------------------------------------------------------------------
// fp16 tensor-core flash attention: register-passed P + ldmatrix K/V loads
// (V via ldmatrix.trans — hardware transpose). 128 thr (4 warps),
// 128 q-rows/CTA, M=32/warp. KV 64-row tiles, cp.async double-buffered.
// ---------------------------------------------------------------------------
#define FKT 64
#define FNT (SEQ / FKT)   // 32
#define KVROW 144         // bytes per KV row (64 halves + 8 pad)
#define KBUF (FKT * KVROW)        // 9216
#define B_K 0
#define B_V (2 * KBUF)            // 18432
#define B_M (4 * KBUF)            // 36864 (mask region)
#define FLASH_SMEM_BYTES (B_M + 2 * FKT * 4)  // 37376

#define CS 0.18033688f  // 0.125 * log2(e)

__global__ __launch_bounds__(128) void flash_attn_tc(const int* __restrict__ mask,
                                                     __half* __restrict__ Out) {
    extern __shared__ char smem[];
    const uint32_t sbase = smem_u32(smem);

    const int b = blockIdx.z;
    const int h = blockIdx.y;
    const int tid = threadIdx.x;
    const int w = tid >> 5;
    const int lane = tid & 31;
    const int g = lane >> 2;
    const int tig = lane & 3;
    const int jL = lane >> 3;      // ldmatrix matrix index
    const int iL = lane & 7;       // row within matrix
    const int qr0 = blockIdx.x * 128 + w * 32;

    const __half* Qp = g_Q + ((size_t)((b * NH + h) * SEQ) + qr0) * HD;
    const __half* Kb = g_K + ((size_t)((b * NH + h) * SEQ)) * HD;
    const __half* Vb = g_V + ((size_t)((b * NH + h) * SEQ)) * HD;
    const int* mb = mask + b * SEQ;

    // Persistent Q A-fragments (fp16, half2-packed)
    uint32_t aQ[2][4][4];
#pragma unroll
    for (int mi = 0; mi < 2; mi++) {
        const __half* Qm = Qp + (size_t)(16 * mi) * HD;
#pragma unroll
        for (int s = 0; s < 4; s++) {
            aQ[mi][s][0] = *(const uint32_t*)&Qm[g * HD + s * 16 + tig * 2];
            aQ[mi][s][1] = *(const uint32_t*)&Qm[(g + 8) * HD + s * 16 + tig * 2];
            aQ[mi][s][2] = *(const uint32_t*)&Qm[g * HD + s * 16 + 8 + tig * 2];
            aQ[mi][s][3] = *(const uint32_t*)&Qm[(g + 8) * HD + s * 16 + 8 + tig * 2];
        }
    }

    float oacc[2][8][4];
#pragma unroll
    for (int mi = 0; mi < 2; mi++)
#pragma unroll
        for (int j = 0; j < 8; j++)
#pragma unroll
            for (int c = 0; c < 4; c++) oacc[mi][j][c] = 0.f;
    float mrun[4] = {-1e30f, -1e30f, -1e30f, -1e30f};
    float lrun[4] = {0.f, 0.f, 0.f, 0.f};

    auto stage = [&](int kt, int buf) {
        const __half* Kg = Kb + (size_t)kt * FKT * HD;
        const __half* Vg = Vb + (size_t)kt * FKT * HD;
        const uint32_t dK = sbase + B_K + buf * KBUF;
        const uint32_t dV = sbase + B_V + buf * KBUF;
#pragma unroll
        for (int t = 0; t < 4; t++) {
            int idx = tid + t * 128;       // 0..511
            int row = idx >> 3;            // 0..63
            int c = idx & 7;               // 16B chunk
            CP_ASYNC16(dK + row * KVROW + c * 16, &Kg[row * HD + c * 8]);
            CP_ASYNC16(dV + row * KVROW + c * 16, &Vg[row * HD + c * 8]);
        }
        if (tid < FKT) {
            CP_ASYNC4(sbase + B_M + buf * (FKT * 4) + tid * 4, &mb[kt * FKT + tid]);
        }
    };

    stage(0, 0);
    CP_ASYNC_COMMIT();

    // K ldmatrix: matrix j -> (n_off = (j>>1)*8, k16B_off = j&1)
    const int knrow_base = (jL >> 1) * 8 + iL;   // + 16*kg
    const int kcol = (jL & 1) * 16;              // + 32*s
    // V trans ldmatrix: matrix j -> (k_off = (j&1)*8, n16B_off = (j>>1)*16)
    const int vkrow_base = (jL & 1) * 8 + iL;    // + 16*s2
    const int vcol = (jL >> 1) * 16;             // + 32*vg

    for (int kt = 0; kt < FNT; kt++) {
        if (kt + 1 < FNT) {
            stage(kt + 1, (kt + 1) & 1);
            CP_ASYNC_COMMIT();
            CP_ASYNC_WAIT(1);
        } else {
            CP_ASYNC_WAIT(0);
        }
        __syncthreads();

        const int buf = kt & 1;
        const uint32_t Kbuf = sbase + B_K + buf * KBUF;
        const uint32_t Vbuf = sbase + B_V + buf * KBUF;
        const int* mk = (const int*)(smem + B_M + buf * (FKT * 4));

        // ---- S = Q @ K^T (32 x 64 per warp), 4 k16-steps ----
        float sc[2][8][4];
#pragma unroll
        for (int mi = 0; mi < 2; mi++)
#pragma unroll
            for (int j = 0; j < 8; j++)
#pragma unroll
                for (int c = 0; c < 4; c++) sc[mi][j][c] = 0.f;
#pragma unroll
        for (int s = 0; s < 4; s++) {
            uint32_t bf[8][2];
#pragma unroll
            for (int kg = 0; kg < 4; kg++) {
                uint32_t ad = Kbuf + (16 * kg + knrow_base) * KVROW + s * 32 + kcol;
                LDSM_X4(bf[2 * kg][0], bf[2 * kg][1],
                        bf[2 * kg + 1][0], bf[2 * kg + 1][1], ad);
            }
#pragma unroll
            for (int jn = 0; jn < 8; jn++) {
                MMA_F16(sc[0][jn], aQ[0][s], bf[jn]);
                MMA_F16(sc[1][jn], aQ[1][s], bf[jn]);
            }
        }

        // ---- online softmax (log2 domain), per m-tile ----
#pragma unroll
        for (int mi = 0; mi < 2; mi++) {
#pragma unroll
            for (int jn = 0; jn < 8; jn++) {
                int2 mv = *(const int2*)&mk[8 * jn + 2 * tig];
                float ax = mv.x ? -1e30f : 0.f;
                float ay = mv.y ? -1e30f : 0.f;
                sc[mi][jn][0] = fmaf(sc[mi][jn][0], CS, ax);
                sc[mi][jn][1] = fmaf(sc[mi][jn][1], CS, ay);
                sc[mi][jn][2] = fmaf(sc[mi][jn][2], CS, ax);
                sc[mi][jn][3] = fmaf(sc[mi][jn][3], CS, ay);
            }
            float mx0 = -1e30f, mx1 = -1e30f;
#pragma unroll
            for (int jn = 0; jn < 8; jn++) {
                mx0 = fmaxf(mx0, fmaxf(sc[mi][jn][0], sc[mi][jn][1]));
                mx1 = fmaxf(mx1, fmaxf(sc[mi][jn][2], sc[mi][jn][3]));
            }
            mx0 = fmaxf(mx0, __shfl_xor_sync(0xFFFFFFFF, mx0, 1));
            mx0 = fmaxf(mx0, __shfl_xor_sync(0xFFFFFFFF, mx0, 2));
            mx1 = fmaxf(mx1, __shfl_xor_sync(0xFFFFFFFF, mx1, 1));
            mx1 = fmaxf(mx1, __shfl_xor_sync(0xFFFFFFFF, mx1, 2));

            const float nm0 = fmaxf(mrun[2 * mi], mx0);
            const float nm1 = fmaxf(mrun[2 * mi + 1], mx1);
            const float cor0 = fast_exp2(mrun[2 * mi] - nm0);
            const float cor1 = fast_exp2(mrun[2 * mi + 1] - nm1);
            mrun[2 * mi] = nm0;
            mrun[2 * mi + 1] = nm1;

            float s0 = 0.f, s1 = 0.f;
#pragma unroll
            for (int jn = 0; jn < 8; jn++) {
                sc[mi][jn][0] = fast_exp2(sc[mi][jn][0] - nm0);
                sc[mi][jn][1] = fast_exp2(sc[mi][jn][1] - nm0);
                sc[mi][jn][2] = fast_exp2(sc[mi][jn][2] - nm1);
                sc[mi][jn][3] = fast_exp2(sc[mi][jn][3] - nm1);
                s0 += sc[mi][jn][0] + sc[mi][jn][1];
                s1 += sc[mi][jn][2] + sc[mi][jn][3];
            }
            s0 += __shfl_xor_sync(0xFFFFFFFF, s0, 1);
            s0 += __shfl_xor_sync(0xFFFFFFFF, s0, 2);
            s1 += __shfl_xor_sync(0xFFFFFFFF, s1, 1);
            s1 += __shfl_xor_sync(0xFFFFFFFF, s1, 2);
            lrun[2 * mi] = lrun[2 * mi] * cor0 + s0;
            lrun[2 * mi + 1] = lrun[2 * mi + 1] * cor1 + s1;

#pragma unroll
            for (int j = 0; j < 8; j++) {
                oacc[mi][j][0] *= cor0;
                oacc[mi][j][1] *= cor0;
                oacc[mi][j][2] *= cor1;
                oacc[mi][j][3] *= cor1;
            }
        }

        // ---- O += P @ V: P from sc registers, V via ldmatrix.trans ----
#pragma unroll
        for (int s2 = 0; s2 < 4; s2++) {
            uint32_t pa0[4], pa1[4];
            pa0[0] = pack_h2(sc[0][2 * s2][0],     sc[0][2 * s2][1]);
            pa0[1] = pack_h2(sc[0][2 * s2][2],     sc[0][2 * s2][3]);
            pa0[2] = pack_h2(sc[0][2 * s2 + 1][0], sc[0][2 * s2 + 1][1]);
            pa0[3] = pack_h2(sc[0][2 * s2 + 1][2], sc[0][2 * s2 + 1][3]);
            pa1[0] = pack_h2(sc[1][2 * s2][0],     sc[1][2 * s2][1]);
            pa1[1] = pack_h2(sc[1][2 * s2][2],     sc[1][2 * s2][3]);
            pa1[2] = pack_h2(sc[1][2 * s2 + 1][0], sc[1][2 * s2 + 1][1]);
            pa1[3] = pack_h2(sc[1][2 * s2 + 1][2], sc[1][2 * s2 + 1][3]);

            uint32_t bv[8][2];
#pragma unroll
            for (int vg = 0; vg < 4; vg++) {
                uint32_t ad = Vbuf + (16 * s2 + vkrow_base) * KVROW + vg * 32 + vcol;
                LDSM_X4_T(bv[2 * vg][0], bv[2 * vg][1],
                          bv[2 * vg + 1][0], bv[2 * vg + 1][1], ad);
            }
#pragma unroll
            for (int jn2 = 0; jn2 < 8; jn2++) {
                MMA_F16(oacc[0][jn2], pa0, bv[jn2]);
                MMA_F16(oacc[1][jn2], pa1, bv[jn2]);
            }
        }
        __syncthreads();
    }

    // ---- epilogue: normalize + store fp16 to g_A ----
#pragma unroll
    for (int mi = 0; mi < 2; mi++) {
        const float il0 = 1.f / lrun[2 * mi];
        const float il1 = 1.f / lrun[2 * mi + 1];
        __half* O0 = Out + ((size_t)(b * SEQ + qr0 + 16 * mi + g)) * DIM + h * HD;
        __half* O1 = Out + ((size_t)(b * SEQ + qr0 + 16 * mi + g + 8)) * DIM + h * HD;
#pragma unroll
        for (int jn2 = 0; jn2 < 8; jn2++) {
            *(uint32_t*)&O0[8 * jn2 + 2 * tig] =
                pack_h2(oacc[mi][jn2][0] * il0, oacc[mi][jn2][1] * il0);
            *(uint32_t*)&O1[8 * jn2 + 2 * tig] =
                pack_h2(oacc[mi][jn2][2] * il1, oacc[mi][jn2][3] * il1);
        }
    }
}

// ---------------------------------------------------------------------------
extern "C" void kernel_launch(void* const* d_in, const int* in_sizes, int n_in,
                              void* d_out, int out_size) {
    const float* q  = (const float*)d_in[0];
    const float* k  = (const float*)d_in[1];
    const float* v  = (const float*)d_in[2];
    const int* mask = (const int*)d_in[3];
    const float* Wq = (const float*)d_in[4];
    const float* bq = (const float*)d_in[5];
    const float* Wk = (const float*)d_in[6];
    const float* bk = (const float*)d_in[7];
    const float* Wv = (const float*)d_in[8];
    const float* bv = (const float*)d_in[9];
    const float* Wo = (const float*)d_in[10];
    const float* bo = (const float*)d_in[11];
    float* out = (float*)d_out;

    __half *pQ, *pK, *pV, *pA, *pWh, *pXh;
    cudaGetSymbolAddress((void**)&pQ, g_Q);
    cudaGetSymbolAddress((void**)&pK, g_K);
    cudaGetSymbolAddress((void**)&pV, g_V);
    cudaGetSymbolAddress((void**)&pA, g_A);
    cudaGetSymbolAddress((void**)&pWh, g_Wh);
    cudaGetSymbolAddress((void**)&pXh, g_Xh);

    cudaFuncSetAttribute(gemm_qkv, cudaFuncAttributeMaxDynamicSharedMemorySize, SM_GEMM_TOTAL);
    cudaFuncSetAttribute(gemm_out, cudaFuncAttributeMaxDynamicSharedMemorySize, SM_GEMM_TOTAL);
    cudaFuncSetAttribute(flash_attn_tc, cudaFuncAttributeMaxDynamicSharedMemorySize, FLASH_SMEM_BYTES);

    // --- fused fp32 -> fp16 pre-pass ---
    const int W8 = DIM * DIM / 8;       // 131072
    const int X8 = MROWS * DIM / 8;     // 524288
    ConvArgs ca;
    ca.src[0] = Wq; ca.dst[0] = pWh + 0 * (size_t)DIM * DIM; ca.n8[0] = W8;
    ca.src[1] = Wk; ca.dst[1] = pWh + 1 * (size_t)DIM * DIM; ca.n8[1] = W8;
    ca.src[2] = Wv; ca.dst[2] = pWh + 2 * (size_t)DIM * DIM; ca.n8[2] = W8;
    ca.src[3] = Wo; ca.dst[3] = pWh + 3 * (size_t)DIM * DIM; ca.n8[3] = W8;
    ca.src[4] = q;  ca.dst[4] = pXh + 0 * (size_t)MROWS * DIM; ca.n8[4] = X8;
    ca.src[5] = k;  ca.dst[5] = pXh + 1 * (size_t)MROWS * DIM; ca.n8[5] = X8;
    ca.src[6] = v;  ca.dst[6] = pXh + 2 * (size_t)MROWS * DIM; ca.n8[6] = X8;
    conv_f16_all<<<dim3(X8 / 1024, 7), 256>>>(ca);

    GemmArgs aq{pXh + 0 * (size_t)MROWS * DIM, pWh + 0 * (size_t)DIM * DIM, bq, pQ};
    GemmArgs ak{pXh + 1 * (size_t)MROWS * DIM, pWh + 1 * (size_t)DIM * DIM, bk, pK};
    GemmArgs av{pXh + 2 * (size_t)MROWS * DIM, pWh + 2 * (size_t)DIM * DIM, bv, pV};

    dim3 gqkv(DIM / GBN, MROWS / GBM, 3);   // (8, 32, 3) = 768 CTAs
    gemm_qkv<<<gqkv, 256, SM_GEMM_TOTAL>>>(aq, ak, av);

    flash_attn_tc<<<dim3(SEQ / 128, NH, BATCH), 128, FLASH_SMEM_BYTES>>>(mask, pA);

    dim3 go(DIM / GBN, MROWS / GBM);        // (8, 32) = 256 CTAs
    gemm_out<<<go, 256, SM_GEMM_TOTAL>>>(pA, pWh + 3 * (size_t)DIM * DIM, bo, out);
}

// round 13
// speedup vs baseline: 1.9723x; 1.0086x over previous
#include <cuda_runtime.h>
#include <cuda_fp16.h>
#include <cstdint>

// Problem constants
#define BATCH 2
#define SEQ   2048
#define DIM   1024
#define NH    16
#define HD    64
#define MROWS (BATCH * SEQ)   // 4096

// Scratch (allocation-free rule: __device__ globals)
__device__ __half g_Q[BATCH * NH * SEQ * HD];  // [b,h,s,hd] fp16
__device__ __half g_K[BATCH * NH * SEQ * HD];
__device__ __half g_V[BATCH * NH * SEQ * HD];
__device__ __half g_A[BATCH * SEQ * DIM];      // attn out [b,s,h*hd] fp16
__device__ __half g_Wh[4 * DIM * DIM];         // fp16 Wq,Wk,Wv,Wo
__device__ __half g_Xh[3 * (size_t)MROWS * DIM]; // fp16 q,k,v

// ---------------------------------------------------------------------------
// Helpers
// ---------------------------------------------------------------------------
__device__ __forceinline__ uint32_t smem_u32(const void* p) {
    uint32_t a;
    asm("{ .reg .u64 t; cvta.to.shared.u64 t, %1; cvt.u32.u64 %0, t; }" : "=r"(a) : "l"(p));
    return a;
}

#define CP_ASYNC16(dst, src) \
    asm volatile("cp.async.cg.shared.global [%0], [%1], 16;" :: "r"(dst), "l"(src))
#define CP_ASYNC4(dst, src) \
    asm volatile("cp.async.ca.shared.global [%0], [%1], 4;" :: "r"(dst), "l"(src))
#define CP_ASYNC_COMMIT() asm volatile("cp.async.commit_group;" ::: "memory")
#define CP_ASYNC_WAIT(n)  asm volatile("cp.async.wait_group %0;" :: "n"(n) : "memory")

// fp16 MMA, fp32 accumulate: m16n8k16
#define MMA_F16(d, av, bv)                                                    \
    asm volatile("mma.sync.aligned.m16n8k16.row.col.f32.f16.f16.f32 "         \
                 "{%0,%1,%2,%3}, {%4,%5,%6,%7}, {%8,%9}, {%0,%1,%2,%3};"      \
                 : "+f"((d)[0]), "+f"((d)[1]), "+f"((d)[2]), "+f"((d)[3])     \
                 : "r"((av)[0]), "r"((av)[1]), "r"((av)[2]), "r"((av)[3]),    \
                   "r"((bv)[0]), "r"((bv)[1]))

#define LDSM_X4(r0, r1, r2, r3, addr)                                         \
    asm volatile("ldmatrix.sync.aligned.m8n8.x4.shared.b16 {%0,%1,%2,%3}, [%4];" \
                 : "=r"(r0), "=r"(r1), "=r"(r2), "=r"(r3) : "r"(addr))

#define LDSM_X4_T(r0, r1, r2, r3, addr)                                       \
    asm volatile("ldmatrix.sync.aligned.m8n8.x4.trans.shared.b16 {%0,%1,%2,%3}, [%4];" \
                 : "=r"(r0), "=r"(r1), "=r"(r2), "=r"(r3) : "r"(addr))

__device__ __forceinline__ uint32_t pack_h2(float a, float b) {
    __half2 h = __floats2half2_rn(a, b);
    return *(uint32_t*)&h;
}

// Fast exp2 on the FMA pipe. Rel err ~3e-6.
__device__ __forceinline__ float fast_exp2(float x) {
    x = fmaxf(x, -126.0f);
    float t = x + 12582912.0f;            // 2^23 + 2^22
    float i = t - 12582912.0f;
    float f = x - i;
    float p = 1.3333558e-3f;
    p = fmaf(p, f, 9.6181291e-3f);
    p = fmaf(p, f, 5.5504109e-2f);
    p = fmaf(p, f, 2.4022651e-1f);
    p = fmaf(p, f, 6.9314718e-1f);
    p = fmaf(p, f, 1.0f);
    int ib = __float_as_int(t) << 23;     // == i << 23 exactly
    return __int_as_float(__float_as_int(p) + ib);
}

// ---------------------------------------------------------------------------
// Fused fp32 -> fp16 conversion pre-pass (7 arrays, one launch).
// ---------------------------------------------------------------------------
struct ConvArgs {
    const float* src[7];
    __half* dst[7];
    int n8[7];     // number of 8-float groups
};

__global__ __launch_bounds__(256) void conv_f16_all(ConvArgs a) {
    const int seg = blockIdx.y;
    const float* src = a.src[seg];
    __half* dst = a.dst[seg];
    const int n8 = a.n8[seg];
    int i0 = blockIdx.x * 1024 + threadIdx.x;
    if (i0 >= n8) return;
#pragma unroll
    for (int t = 0; t < 4; t++) {
        int idx = i0 + t * 256;
        if (idx < n8) {
            float4 v0 = ((const float4*)src)[2 * idx];
            float4 v1 = ((const float4*)src)[2 * idx + 1];
            uint4 o;
            o.x = pack_h2(v0.x, v0.y);
            o.y = pack_h2(v0.z, v0.w);
            o.z = pack_h2(v1.x, v1.y);
            o.w = pack_h2(v1.z, v1.w);
            ((uint4*)dst)[idx] = o;
        }
    }
}

// ---------------------------------------------------------------------------
// fp16 mma.sync GEMM, 3-stage cp.async ring, ONE __syncthreads per k-tile.
// CTA tile 128x128, BK=64, 256 threads = 8 warps (4m x 2n), 32x64. 2 CTAs/SM.
// ---------------------------------------------------------------------------
#define GBM 128
#define GBN 128
#define GBK 64
#define NKT (DIM / GBK)                 // 16
#define SA_BYTES (GBM * GBK * 2)        // 16384
#define SB_BYTES (GBN * GBK * 2)        // 16384
#define NSTAGE 3
#define SM_GEMM_TOTAL (NSTAGE * (SA_BYTES + SB_BYTES))   // 98304

struct GemmArgs {
    const __half* A;
    const __half* W;
    const float* bias;
    void* C;
};

template <int SPLIT_HEADS>
__device__ __forceinline__ void gemm_body(const __half* __restrict__ A,
                                          const __half* __restrict__ W,
                                          const float* __restrict__ bias,
                                          void* __restrict__ Cv) {
    extern __shared__ char smem[];
    const uint32_t sA = smem_u32(smem);
    const uint32_t sB = sA + NSTAGE * SA_BYTES;

    const int tid = threadIdx.x;
    const int lane = tid & 31;
    const int wid = tid >> 5;      // 0..7
    const int wm = wid & 3;        // 0..3 (m: 4 x 32)
    const int wn = wid >> 2;       // 0..1 (n: 2 x 64)
    const int g = lane >> 2;
    const int tig = lane & 3;
    const int m0 = blockIdx.y * GBM;
    const int n0 = blockIdx.x * GBN;

    // ldmatrix lane decomposition
    const int jL = lane >> 3;
    const int iL = lane & 7;
    const int rA0 = wm * 32 + (jL & 1) * 8 + iL;
    const int rA1 = rA0 + 16;
    const int cA = jL >> 1;
    const int cB = jL & 1;
    int rB[4];
#pragma unroll
    for (int bg = 0; bg < 4; bg++) rB[bg] = wn * 64 + bg * 16 + (jL >> 1) * 8 + iL;

    float acc[2][8][4];
#pragma unroll
    for (int i = 0; i < 2; i++)
#pragma unroll
        for (int j = 0; j < 8; j++)
#pragma unroll
            for (int c = 0; c < 4; c++) acc[i][j][c] = 0.f;

    auto stage = [&](int kt, int buf) {
        const int k0 = kt * GBK;    // halves
#pragma unroll
        for (int t = 0; t < 4; t++) {
            int idx = tid + t * 256;
            int row = idx >> 3;
            int c = idx & 7;
            uint32_t dst = sA + buf * SA_BYTES + row * 128 + ((c ^ (row & 7)) << 4);
            CP_ASYNC16(dst, &A[(size_t)(m0 + row) * DIM + k0 + c * 8]);
        }
#pragma unroll
        for (int t = 0; t < 4; t++) {
            int idx = tid + t * 256;
            int row = idx >> 3;
            int c = idx & 7;
            uint32_t dst = sB + buf * SB_BYTES + row * 128 + ((c ^ (row & 7)) << 4);
            CP_ASYNC16(dst, &W[(size_t)(n0 + row) * DIM + k0 + c * 8]);
        }
    };

    stage(0, 0);
    CP_ASYNC_COMMIT();
    stage(1, 1);
    CP_ASYNC_COMMIT();

    int bi = 0;         // buffer of tile kt
    int bs = 2;         // buffer for tile kt+2
    for (int kt = 0; kt < NKT; kt++) {
        if (kt < NKT - 1) {
            CP_ASYNC_WAIT(1);
        } else {
            CP_ASYNC_WAIT(0);
        }
        __syncthreads();
        if (kt + 2 < NKT) {
            stage(kt + 2, bs);
            CP_ASYNC_COMMIT();
        }

        const uint32_t abuf = sA + bi * SA_BYTES;
        const uint32_t bbuf = sB + bi * SB_BYTES;
#pragma unroll
        for (int s = 0; s < 4; s++) {
            uint32_t a[2][4];
            {
                int ch = 2 * s + cA;
                uint32_t ad0 = abuf + rA0 * 128 + ((ch ^ (rA0 & 7)) << 4);
                uint32_t ad1 = abuf + rA1 * 128 + ((ch ^ (rA1 & 7)) << 4);
                LDSM_X4(a[0][0], a[0][1], a[0][2], a[0][3], ad0);
                LDSM_X4(a[1][0], a[1][1], a[1][2], a[1][3], ad1);
            }
            uint32_t bf[8][2];
            {
                int ch = 2 * s + cB;
#pragma unroll
                for (int bg = 0; bg < 4; bg++) {
                    uint32_t ad = bbuf + rB[bg] * 128 + ((ch ^ (rB[bg] & 7)) << 4);
                    LDSM_X4(bf[2 * bg][0], bf[2 * bg][1],
                            bf[2 * bg + 1][0], bf[2 * bg + 1][1], ad);
                }
            }
#pragma unroll
            for (int i = 0; i < 2; i++)
#pragma unroll
                for (int j = 0; j < 8; j++) MMA_F16(acc[i][j], a[i], bf[j]);
        }
        bi = (bi == NSTAGE - 1) ? 0 : bi + 1;
        bs = (bs == NSTAGE - 1) ? 0 : bs + 1;
    }

#pragma unroll
    for (int i = 0; i < 2; i++) {
        const int m1 = m0 + wm * 32 + i * 16 + g;
        const int m2 = m1 + 8;
#pragma unroll
        for (int j = 0; j < 8; j++) {
            const int n = n0 + wn * 64 + j * 8 + tig * 2;
            const float2 bb = *(const float2*)&bias[n];
            if (SPLIT_HEADS) {
                __half* C = (__half*)Cv;
                uint32_t h1 = pack_h2(acc[i][j][0] + bb.x, acc[i][j][1] + bb.y);
                uint32_t h2 = pack_h2(acc[i][j][2] + bb.x, acc[i][j][3] + bb.y);
                int h = n >> 6;
                int hd = n & (HD - 1);
                {
                    int b = m1 >> 11, sq = m1 & (SEQ - 1);
                    *(uint32_t*)&C[((size_t)((b * NH + h) * SEQ + sq)) * HD + hd] = h1;
                }
                {
                    int b = m2 >> 11, sq = m2 & (SEQ - 1);
                    *(uint32_t*)&C[((size_t)((b * NH + h) * SEQ + sq)) * HD + hd] = h2;
                }
            } else {
                float* C = (float*)Cv;
                float2 r1, r2;
                r1.x = acc[i][j][0] + bb.x;
                r1.y = acc[i][j][1] + bb.y;
                r2.x = acc[i][j][2] + bb.x;
                r2.y = acc[i][j][3] + bb.y;
                *(float2*)&C[(size_t)m1 * DIM + n] = r1;
                *(float2*)&C[(size_t)m2 * DIM + n] = r2;
            }
        }
    }
}

__global__ __launch_bounds__(256, 2) void gemm_qkv(GemmArgs a0, GemmArgs a1, GemmArgs a2) {
    const GemmArgs& a = (blockIdx.z == 0) ? a0 : (blockIdx.z == 1) ? a1 : a2;
    gemm_body<1>(a.A, a.W, a.bias, a.C);
}

__global__ __launch_bounds__(256, 2) void gemm_out(const __half* __restrict__ A,
                                                   const __half* __restrict__ W,
                                                   const float* __restrict__ bias,
                                                   float* __restrict__ C) {
    gemm_body<0>(A, W, bias, C);
}

// ---------------------------------------------------------------------------
// fp16 flash attention: register-passed P, ldmatrix K/V, 3-stage KV ring,
// ONE __syncthreads per kv-tile. 128 thr (4 warps), 128 q-rows/CTA.
// ---------------------------------------------------------------------------
#define FKT 64
#define FNT (SEQ / FKT)   // 32
#define KVROW 144         // bytes per KV row (64 halves + 8 pad)
#define KBUF (FKT * KVROW)        // 9216
#define B_K 0
#define B_V (3 * KBUF)            // 27648
#define B_M (6 * KBUF)            // 55296 (mask region: 3 x 256B)
#define FLASH_SMEM_BYTES (B_M + 3 * FKT * 4)  // 56064

#define CS 0.18033688f  // 0.125 * log2(e)

__global__ __launch_bounds__(128) void flash_attn_tc(const int* __restrict__ mask,
                                                     __half* __restrict__ Out) {
    extern __shared__ char smem[];
    const uint32_t sbase = smem_u32(smem);

    const int b = blockIdx.z;
    const int h = blockIdx.y;
    const int tid = threadIdx.x;
    const int w = tid >> 5;
    const int lane = tid & 31;
    const int g = lane >> 2;
    const int tig = lane & 3;
    const int jL = lane >> 3;
    const int iL = lane & 7;
    const int qr0 = blockIdx.x * 128 + w * 32;

    const __half* Qp = g_Q + ((size_t)((b * NH + h) * SEQ) + qr0) * HD;
    const __half* Kb = g_K + ((size_t)((b * NH + h) * SEQ)) * HD;
    const __half* Vb = g_V + ((size_t)((b * NH + h) * SEQ)) * HD;
    const int* mb = mask + b * SEQ;

    // Persistent Q A-fragments
    uint32_t aQ[2][4][4];
#pragma unroll
    for (int mi = 0; mi < 2; mi++) {
        const __half* Qm = Qp + (size_t)(16 * mi) * HD;
#pragma unroll
        for (int s = 0; s < 4; s++) {
            aQ[mi][s][0] = *(const uint32_t*)&Qm[g * HD + s * 16 + tig * 2];
            aQ[mi][s][1] = *(const uint32_t*)&Qm[(g + 8) * HD + s * 16 + tig * 2];
            aQ[mi][s][2] = *(const uint32_t*)&Qm[g * HD + s * 16 + 8 + tig * 2];
            aQ[mi][s][3] = *(const uint32_t*)&Qm[(g + 8) * HD + s * 16 + 8 + tig * 2];
        }
    }

    float oacc[2][8][4];
#pragma unroll
    for (int mi = 0; mi < 2; mi++)
#pragma unroll
        for (int j = 0; j < 8; j++)
#pragma unroll
            for (int c = 0; c < 4; c++) oacc[mi][j][c] = 0.f;
    float mrun[4] = {-1e30f, -1e30f, -1e30f, -1e30f};
    float lrun[4] = {0.f, 0.f, 0.f, 0.f};

    auto stage = [&](int kt, int buf) {
        const __half* Kg = Kb + (size_t)kt * FKT * HD;
        const __half* Vg = Vb + (size_t)kt * FKT * HD;
        const uint32_t dK = sbase + B_K + buf * KBUF;
        const uint32_t dV = sbase + B_V + buf * KBUF;
#pragma unroll
        for (int t = 0; t < 4; t++) {
            int idx = tid + t * 128;       // 0..511
            int row = idx >> 3;            // 0..63
            int c = idx & 7;               // 16B chunk
            CP_ASYNC16(dK + row * KVROW + c * 16, &Kg[row * HD + c * 8]);
            CP_ASYNC16(dV + row * KVROW + c * 16, &Vg[row * HD + c * 8]);
        }
        if (tid < FKT) {
            CP_ASYNC4(sbase + B_M + buf * (FKT * 4) + tid * 4, &mb[kt * FKT + tid]);
        }
    };

    stage(0, 0);
    CP_ASYNC_COMMIT();
    stage(1, 1);
    CP_ASYNC_COMMIT();

    // K ldmatrix: matrix j -> (n_off = (j>>1)*8, k16B_off = j&1)
    const int knrow_base = (jL >> 1) * 8 + iL;
    const int kcol = (jL & 1) * 16;
    // V trans ldmatrix: matrix j -> (k_off = (j&1)*8, n16B_off = (j>>1)*16)
    const int vkrow_base = (jL & 1) * 8 + iL;
    const int vcol = (jL >> 1) * 16;

    int bi = 0, bs = 2;
    for (int kt = 0; kt < FNT; kt++) {
        if (kt < FNT - 1) {
            CP_ASYNC_WAIT(1);
        } else {
            CP_ASYNC_WAIT(0);
        }
        __syncthreads();
        if (kt + 2 < FNT) {
            stage(kt + 2, bs);
            CP_ASYNC_COMMIT();
        }

        const uint32_t Kbuf = sbase + B_K + bi * KBUF;
        const uint32_t Vbuf = sbase + B_V + bi * KBUF;
        const int* mk = (const int*)(smem + B_M + bi * (FKT * 4));

        // ---- S = Q @ K^T (32 x 64 per warp), 4 k16-steps ----
        float sc[2][8][4];
#pragma unroll
        for (int mi = 0; mi < 2; mi++)
#pragma unroll
            for (int j = 0; j < 8; j++)
#pragma unroll
                for (int c = 0; c < 4; c++) sc[mi][j][c] = 0.f;
#pragma unroll
        for (int s = 0; s < 4; s++) {
            uint32_t bf[8][2];
#pragma unroll
            for (int kg = 0; kg < 4; kg++) {
                uint32_t ad = Kbuf + (16 * kg + knrow_base) * KVROW + s * 32 + kcol;
                LDSM_X4(bf[2 * kg][0], bf[2 * kg][1],
                        bf[2 * kg + 1][0], bf[2 * kg + 1][1], ad);
            }
#pragma unroll
            for (int jn = 0; jn < 8; jn++) {
                MMA_F16(sc[0][jn], aQ[0][s], bf[jn]);
                MMA_F16(sc[1][jn], aQ[1][s], bf[jn]);
            }
        }

        // ---- online softmax (log2 domain), per m-tile ----
#pragma unroll
        for (int mi = 0; mi < 2; mi++) {
#pragma unroll
            for (int jn = 0; jn < 8; jn++) {
                int2 mv = *(const int2*)&mk[8 * jn + 2 * tig];
                float ax = mv.x ? -1e30f : 0.f;
                float ay = mv.y ? -1e30f : 0.f;
                sc[mi][jn][0] = fmaf(sc[mi][jn][0], CS, ax);
                sc[mi][jn][1] = fmaf(sc[mi][jn][1], CS, ay);
                sc[mi][jn][2] = fmaf(sc[mi][jn][2], CS, ax);
                sc[mi][jn][3] = fmaf(sc[mi][jn][3], CS, ay);
            }
            float mx0 = -1e30f, mx1 = -1e30f;
#pragma unroll
            for (int jn = 0; jn < 8; jn++) {
                mx0 = fmaxf(mx0, fmaxf(sc[mi][jn][0], sc[mi][jn][1]));
                mx1 = fmaxf(mx1, fmaxf(sc[mi][jn][2], sc[mi][jn][3]));
            }
            mx0 = fmaxf(mx0, __shfl_xor_sync(0xFFFFFFFF, mx0, 1));
            mx0 = fmaxf(mx0, __shfl_xor_sync(0xFFFFFFFF, mx0, 2));
            mx1 = fmaxf(mx1, __shfl_xor_sync(0xFFFFFFFF, mx1, 1));
            mx1 = fmaxf(mx1, __shfl_xor_sync(0xFFFFFFFF, mx1, 2));

            const float nm0 = fmaxf(mrun[2 * mi], mx0);
            const float nm1 = fmaxf(mrun[2 * mi + 1], mx1);
            const float cor0 = fast_exp2(mrun[2 * mi] - nm0);
            const float cor1 = fast_exp2(mrun[2 * mi + 1] - nm1);
            mrun[2 * mi] = nm0;
            mrun[2 * mi + 1] = nm1;

            float s0 = 0.f, s1 = 0.f;
#pragma unroll
            for (int jn = 0; jn < 8; jn++) {
                sc[mi][jn][0] = fast_exp2(sc[mi][jn][0] - nm0);
                sc[mi][jn][1] = fast_exp2(sc[mi][jn][1] - nm0);
                sc[mi][jn][2] = fast_exp2(sc[mi][jn][2] - nm1);
                sc[mi][jn][3] = fast_exp2(sc[mi][jn][3] - nm1);
                s0 += sc[mi][jn][0] + sc[mi][jn][1];
                s1 += sc[mi][jn][2] + sc[mi][jn][3];
            }
            s0 += __shfl_xor_sync(0xFFFFFFFF, s0, 1);
            s0 += __shfl_xor_sync(0xFFFFFFFF, s0, 2);
            s1 += __shfl_xor_sync(0xFFFFFFFF, s1, 1);
            s1 += __shfl_xor_sync(0xFFFFFFFF, s1, 2);
            lrun[2 * mi] = lrun[2 * mi] * cor0 + s0;
            lrun[2 * mi + 1] = lrun[2 * mi + 1] * cor1 + s1;

#pragma unroll
            for (int j = 0; j < 8; j++) {
                oacc[mi][j][0] *= cor0;
                oacc[mi][j][1] *= cor0;
                oacc[mi][j][2] *= cor1;
                oacc[mi][j][3] *= cor1;
            }
        }

        // ---- O += P @ V: P from sc registers, V via ldmatrix.trans ----
#pragma unroll
        for (int s2 = 0; s2 < 4; s2++) {
            uint32_t pa0[4], pa1[4];
            pa0[0] = pack_h2(sc[0][2 * s2][0],     sc[0][2 * s2][1]);
            pa0[1] = pack_h2(sc[0][2 * s2][2],     sc[0][2 * s2][3]);
            pa0[2] = pack_h2(sc[0][2 * s2 + 1][0], sc[0][2 * s2 + 1][1]);
            pa0[3] = pack_h2(sc[0][2 * s2 + 1][2], sc[0][2 * s2 + 1][3]);
            pa1[0] = pack_h2(sc[1][2 * s2][0],     sc[1][2 * s2][1]);
            pa1[1] = pack_h2(sc[1][2 * s2][2],     sc[1][2 * s2][3]);
            pa1[2] = pack_h2(sc[1][2 * s2 + 1][0], sc[1][2 * s2 + 1][1]);
            pa1[3] = pack_h2(sc[1][2 * s2 + 1][2], sc[1][2 * s2 + 1][3]);

            uint32_t bv[8][2];
#pragma unroll
            for (int vg = 0; vg < 4; vg++) {
                uint32_t ad = Vbuf + (16 * s2 + vkrow_base) * KVROW + vg * 32 + vcol;
                LDSM_X4_T(bv[2 * vg][0], bv[2 * vg][1],
                          bv[2 * vg + 1][0], bv[2 * vg + 1][1], ad);
            }
#pragma unroll
            for (int jn2 = 0; jn2 < 8; jn2++) {
                MMA_F16(oacc[0][jn2], pa0, bv[jn2]);
                MMA_F16(oacc[1][jn2], pa1, bv[jn2]);
            }
        }
        bi = (bi == 2) ? 0 : bi + 1;
        bs = (bs == 2) ? 0 : bs + 1;
    }

    // ---- epilogue: normalize + store fp16 to g_A ----
#pragma unroll
    for (int mi = 0; mi < 2; mi++) {
        const float il0 = 1.f / lrun[2 * mi];
        const float il1 = 1.f / lrun[2 * mi + 1];
        __half* O0 = Out + ((size_t)(b * SEQ + qr0 + 16 * mi + g)) * DIM + h * HD;
        __half* O1 = Out + ((size_t)(b * SEQ + qr0 + 16 * mi + g + 8)) * DIM + h * HD;
#pragma unroll
        for (int jn2 = 0; jn2 < 8; jn2++) {
            *(uint32_t*)&O0[8 * jn2 + 2 * tig] =
                pack_h2(oacc[mi][jn2][0] * il0, oacc[mi][jn2][1] * il0);
            *(uint32_t*)&O1[8 * jn2 + 2 * tig] =
                pack_h2(oacc[mi][jn2][2] * il1, oacc[mi][jn2][3] * il1);
        }
    }
}

// ---------------------------------------------------------------------------
extern "C" void kernel_launch(void* const* d_in, const int* in_sizes, int n_in,
                              void* d_out, int out_size) {
    const float* q  = (const float*)d_in[0];
    const float* k  = (const float*)d_in[1];
    const float* v  = (const float*)d_in[2];
    const int* mask = (const int*)d_in[3];
    const float* Wq = (const float*)d_in[4];
    const float* bq = (const float*)d_in[5];
    const float* Wk = (const float*)d_in[6];
    const float* bk = (const float*)d_in[7];
    const float* Wv = (const float*)d_in[8];
    const float* bv = (const float*)d_in[9];
    const float* Wo = (const float*)d_in[10];
    const float* bo = (const float*)d_in[11];
    float* out = (float*)d_out;

    __half *pQ, *pK, *pV, *pA, *pWh, *pXh;
    cudaGetSymbolAddress((void**)&pQ, g_Q);
    cudaGetSymbolAddress((void**)&pK, g_K);
    cudaGetSymbolAddress((void**)&pV, g_V);
    cudaGetSymbolAddress((void**)&pA, g_A);
    cudaGetSymbolAddress((void**)&pWh, g_Wh);
    cudaGetSymbolAddress((void**)&pXh, g_Xh);

    cudaFuncSetAttribute(gemm_qkv, cudaFuncAttributeMaxDynamicSharedMemorySize, SM_GEMM_TOTAL);
    cudaFuncSetAttribute(gemm_out, cudaFuncAttributeMaxDynamicSharedMemorySize, SM_GEMM_TOTAL);
    cudaFuncSetAttribute(flash_attn_tc, cudaFuncAttributeMaxDynamicSharedMemorySize, FLASH_SMEM_BYTES);

    // --- fused fp32 -> fp16 pre-pass ---
    const int W8 = DIM * DIM / 8;       // 131072
    const int X8 = MROWS * DIM / 8;     // 524288
    ConvArgs ca;
    ca.src[0] = Wq; ca.dst[0] = pWh + 0 * (size_t)DIM * DIM; ca.n8[0] = W8;
    ca.src[1] = Wk; ca.dst[1] = pWh + 1 * (size_t)DIM * DIM; ca.n8[1] = W8;
    ca.src[2] = Wv; ca.dst[2] = pWh + 2 * (size_t)DIM * DIM; ca.n8[2] = W8;
    ca.src[3] = Wo; ca.dst[3] = pWh + 3 * (size_t)DIM * DIM; ca.n8[3] = W8;
    ca.src[4] = q;  ca.dst[4] = pXh + 0 * (size_t)MROWS * DIM; ca.n8[4] = X8;
    ca.src[5] = k;  ca.dst[5] = pXh + 1 * (size_t)MROWS * DIM; ca.n8[5] = X8;
    ca.src[6] = v;  ca.dst[6] = pXh + 2 * (size_t)MROWS * DIM; ca.n8[6] = X8;
    conv_f16_all<<<dim3(X8 / 1024, 7), 256>>>(ca);

    GemmArgs aq{pXh + 0 * (size_t)MROWS * DIM, pWh + 0 * (size_t)DIM * DIM, bq, pQ};
    GemmArgs ak{pXh + 1 * (size_t)MROWS * DIM, pWh + 1 * (size_t)DIM * DIM, bk, pK};
    GemmArgs av{pXh + 2 * (size_t)MROWS * DIM, pWh + 2 * (size_t)DIM * DIM, bv, pV};

    dim3 gqkv(DIM / GBN, MROWS / GBM, 3);   // (8, 32, 3) = 768 CTAs
    gemm_qkv<<<gqkv, 256, SM_GEMM_TOTAL>>>(aq, ak, av);

    flash_attn_tc<<<dim3(SEQ / 128, NH, BATCH), 128, FLASH_SMEM_BYTES>>>(mask, pA);

    dim3 go(DIM / GBN, MROWS / GBM);        // (8, 32) = 256 CTAs
    gemm_out<<<go, 256, SM_GEMM_TOTAL>>>(pA, pWh + 3 * (size_t)DIM * DIM, bo, out);
}

// round 14
// speedup vs baseline: 2.0378x; 1.0332x over previous
#include <cuda_runtime.h>
#include <cuda_fp16.h>
#include <cstdint>

// Problem constants
#define BATCH 2
#define SEQ   2048
#define DIM   1024
#define NH    16
#define HD    64
#define MROWS (BATCH * SEQ)   // 4096

#define FKT 64
#define FNT (SEQ / FKT)   // 32

// Scratch (allocation-free rule: __device__ globals)
__device__ __half g_Q[BATCH * NH * SEQ * HD];  // [b,h,s,hd] fp16, PRE-SCALED by CS
__device__ __half g_K[BATCH * NH * SEQ * HD];
__device__ __half g_V[BATCH * NH * SEQ * HD];
__device__ __half g_A[BATCH * SEQ * DIM];      // attn out [b,s,h*hd] fp16
__device__ __half g_Wh[4 * DIM * DIM];         // fp16 Wq,Wk,Wv,Wo
__device__ __half g_Xh[3 * (size_t)MROWS * DIM]; // fp16 q,k,v
__device__ float  g_bias_m[BATCH * SEQ];       // mask bias: -1e30 or 0
__device__ int    g_mflag[BATCH * FNT];        // per-(b, kv-tile) mask flag

#define CS 0.18033688f  // 0.125 * log2(e)

// ---------------------------------------------------------------------------
// Helpers
// ---------------------------------------------------------------------------
__device__ __forceinline__ uint32_t smem_u32(const void* p) {
    uint32_t a;
    asm("{ .reg .u64 t; cvta.to.shared.u64 t, %1; cvt.u32.u64 %0, t; }" : "=r"(a) : "l"(p));
    return a;
}

#define CP_ASYNC16(dst, src) \
    asm volatile("cp.async.cg.shared.global [%0], [%1], 16;" :: "r"(dst), "l"(src))
#define CP_ASYNC_COMMIT() asm volatile("cp.async.commit_group;" ::: "memory")
#define CP_ASYNC_WAIT(n)  asm volatile("cp.async.wait_group %0;" :: "n"(n) : "memory")

// fp16 MMA, fp32 accumulate: m16n8k16
#define MMA_F16(d, av, bv)                                                    \
    asm volatile("mma.sync.aligned.m16n8k16.row.col.f32.f16.f16.f32 "         \
                 "{%0,%1,%2,%3}, {%4,%5,%6,%7}, {%8,%9}, {%0,%1,%2,%3};"      \
                 : "+f"((d)[0]), "+f"((d)[1]), "+f"((d)[2]), "+f"((d)[3])     \
                 : "r"((av)[0]), "r"((av)[1]), "r"((av)[2]), "r"((av)[3]),    \
                   "r"((bv)[0]), "r"((bv)[1]))

#define LDSM_X4(r0, r1, r2, r3, addr)                                         \
    asm volatile("ldmatrix.sync.aligned.m8n8.x4.shared.b16 {%0,%1,%2,%3}, [%4];" \
                 : "=r"(r0), "=r"(r1), "=r"(r2), "=r"(r3) : "r"(addr))

#define LDSM_X4_T(r0, r1, r2, r3, addr)                                       \
    asm volatile("ldmatrix.sync.aligned.m8n8.x4.trans.shared.b16 {%0,%1,%2,%3}, [%4];" \
                 : "=r"(r0), "=r"(r1), "=r"(r2), "=r"(r3) : "r"(addr))

__device__ __forceinline__ uint32_t pack_h2(float a, float b) {
    __half2 h = __floats2half2_rn(a, b);
    return *(uint32_t*)&h;
}

// Fast exp2 on the FMA pipe, deg-4 poly. Rel err ~4e-5.
__device__ __forceinline__ float fast_exp2(float x) {
    x = fmaxf(x, -126.0f);
    float t = x + 12582912.0f;            // 2^23 + 2^22
    float i = t - 12582912.0f;
    float f = x - i;
    float p = 9.6181291e-3f;
    p = fmaf(p, f, 5.5504109e-2f);
    p = fmaf(p, f, 2.4022651e-1f);
    p = fmaf(p, f, 6.9314718e-1f);
    p = fmaf(p, f, 1.0f);
    int ib = __float_as_int(t) << 23;     // == i << 23 exactly
    return __int_as_float(__float_as_int(p) + ib);
}

// ---------------------------------------------------------------------------
// Fused fp32 -> fp16 conversion pre-pass (7 arrays + mask prep, one launch).
// ---------------------------------------------------------------------------
struct ConvArgs {
    const float* src[7];
    __half* dst[7];
    int n8[7];     // number of 8-float groups
    const int* mask;
    float* bias_m;
    int* mflag;
};

__global__ __launch_bounds__(256) void conv_f16_all(ConvArgs a) {
    const int seg = blockIdx.y;
    const int tid = threadIdx.x;
    if (seg == 7) {
        // mask pre-pass: bias floats + per-tile flags
        if (blockIdx.x != 0) return;
        for (int i = tid; i < BATCH * SEQ; i += 256) {
            a.bias_m[i] = a.mask[i] ? -1e30f : 0.f;
        }
        if (tid < BATCH * FNT) {
            int f = 0;
#pragma unroll 4
            for (int j = 0; j < FKT; j++) f |= a.mask[tid * FKT + j];
            a.mflag[tid] = f ? 1 : 0;
        }
        return;
    }
    const float* src = a.src[seg];
    __half* dst = a.dst[seg];
    const int n8 = a.n8[seg];
    int i0 = blockIdx.x * 1024 + tid;
    if (i0 >= n8) return;
#pragma unroll
    for (int t = 0; t < 4; t++) {
        int idx = i0 + t * 256;
        if (idx < n8) {
            float4 v0 = ((const float4*)src)[2 * idx];
            float4 v1 = ((const float4*)src)[2 * idx + 1];
            uint4 o;
            o.x = pack_h2(v0.x, v0.y);
            o.y = pack_h2(v0.z, v0.w);
            o.z = pack_h2(v1.x, v1.y);
            o.w = pack_h2(v1.z, v1.w);
            ((uint4*)dst)[idx] = o;
        }
    }
}

// ---------------------------------------------------------------------------
// fp16 mma.sync GEMM, 3-stage cp.async ring, one __syncthreads per k-tile.
// CTA tile 128x128, BK=64, 256 threads = 8 warps (4m x 2n), 32x64. 2 CTAs/SM.
// SPLIT_HEADS path multiplies output by args.scale (CS for Q, 1.0 for K/V).
// ---------------------------------------------------------------------------
#define GBM 128
#define GBN 128
#define GBK 64
#define NKT (DIM / GBK)                 // 16
#define SA_BYTES (GBM * GBK * 2)        // 16384
#define SB_BYTES (GBN * GBK * 2)        // 16384
#define NSTAGE 3
#define SM_GEMM_TOTAL (NSTAGE * (SA_BYTES + SB_BYTES))   // 98304

struct GemmArgs {
    const __half* A;
    const __half* W;
    const float* bias;
    void* C;
    float scale;
};

template <int SPLIT_HEADS>
__device__ __forceinline__ void gemm_body(const __half* __restrict__ A,
                                          const __half* __restrict__ W,
                                          const float* __restrict__ bias,
                                          void* __restrict__ Cv,
                                          float scale) {
    extern __shared__ char smem[];
    const uint32_t sA = smem_u32(smem);
    const uint32_t sB = sA + NSTAGE * SA_BYTES;

    const int tid = threadIdx.x;
    const int lane = tid & 31;
    const int wid = tid >> 5;      // 0..7
    const int wm = wid & 3;        // 0..3 (m: 4 x 32)
    const int wn = wid >> 2;       // 0..1 (n: 2 x 64)
    const int g = lane >> 2;
    const int tig = lane & 3;
    const int m0 = blockIdx.y * GBM;
    const int n0 = blockIdx.x * GBN;

    // ldmatrix lane decomposition
    const int jL = lane >> 3;
    const int iL = lane & 7;
    const int rA0 = wm * 32 + (jL & 1) * 8 + iL;
    const int rA1 = rA0 + 16;
    const int cA = jL >> 1;
    const int cB = jL & 1;
    int rB[4];
#pragma unroll
    for (int bg = 0; bg < 4; bg++) rB[bg] = wn * 64 + bg * 16 + (jL >> 1) * 8 + iL;

    float acc[2][8][4];
#pragma unroll
    for (int i = 0; i < 2; i++)
#pragma unroll
        for (int j = 0; j < 8; j++)
#pragma unroll
            for (int c = 0; c < 4; c++) acc[i][j][c] = 0.f;

    auto stage = [&](int kt, int buf) {
        const int k0 = kt * GBK;    // halves
#pragma unroll
        for (int t = 0; t < 4; t++) {
            int idx = tid + t * 256;
            int row = idx >> 3;
            int c = idx & 7;
            uint32_t dst = sA + buf * SA_BYTES + row * 128 + ((c ^ (row & 7)) << 4);
            CP_ASYNC16(dst, &A[(size_t)(m0 + row) * DIM + k0 + c * 8]);
        }
#pragma unroll
        for (int t = 0; t < 4; t++) {
            int idx = tid + t * 256;
            int row = idx >> 3;
            int c = idx & 7;
            uint32_t dst = sB + buf * SB_BYTES + row * 128 + ((c ^ (row & 7)) << 4);
            CP_ASYNC16(dst, &W[(size_t)(n0 + row) * DIM + k0 + c * 8]);
        }
    };

    stage(0, 0);
    CP_ASYNC_COMMIT();
    stage(1, 1);
    CP_ASYNC_COMMIT();

    int bi = 0, bs = 2;
    for (int kt = 0; kt < NKT; kt++) {
        if (kt < NKT - 1) {
            CP_ASYNC_WAIT(1);
        } else {
            CP_ASYNC_WAIT(0);
        }
        __syncthreads();
        if (kt + 2 < NKT) {
            stage(kt + 2, bs);
            CP_ASYNC_COMMIT();
        }

        const uint32_t abuf = sA + bi * SA_BYTES;
        const uint32_t bbuf = sB + bi * SB_BYTES;
#pragma unroll
        for (int s = 0; s < 4; s++) {
            uint32_t a[2][4];
            {
                int ch = 2 * s + cA;
                uint32_t ad0 = abuf + rA0 * 128 + ((ch ^ (rA0 & 7)) << 4);
                uint32_t ad1 = abuf + rA1 * 128 + ((ch ^ (rA1 & 7)) << 4);
                LDSM_X4(a[0][0], a[0][1], a[0][2], a[0][3], ad0);
                LDSM_X4(a[1][0], a[1][1], a[1][2], a[1][3], ad1);
            }
            uint32_t bf[8][2];
            {
                int ch = 2 * s + cB;
#pragma unroll
                for (int bg = 0; bg < 4; bg++) {
                    uint32_t ad = bbuf + rB[bg] * 128 + ((ch ^ (rB[bg] & 7)) << 4);
                    LDSM_X4(bf[2 * bg][0], bf[2 * bg][1],
                            bf[2 * bg + 1][0], bf[2 * bg + 1][1], ad);
                }
            }
#pragma unroll
            for (int i = 0; i < 2; i++)
#pragma unroll
                for (int j = 0; j < 8; j++) MMA_F16(acc[i][j], a[i], bf[j]);
        }
        bi = (bi == NSTAGE - 1) ? 0 : bi + 1;
        bs = (bs == NSTAGE - 1) ? 0 : bs + 1;
    }

#pragma unroll
    for (int i = 0; i < 2; i++) {
        const int m1 = m0 + wm * 32 + i * 16 + g;
        const int m2 = m1 + 8;
#pragma unroll
        for (int j = 0; j < 8; j++) {
            const int n = n0 + wn * 64 + j * 8 + tig * 2;
            const float2 bb = *(const float2*)&bias[n];
            if (SPLIT_HEADS) {
                __half* C = (__half*)Cv;
                uint32_t h1 = pack_h2((acc[i][j][0] + bb.x) * scale,
                                      (acc[i][j][1] + bb.y) * scale);
                uint32_t h2 = pack_h2((acc[i][j][2] + bb.x) * scale,
                                      (acc[i][j][3] + bb.y) * scale);
                int h = n >> 6;
                int hd = n & (HD - 1);
                {
                    int b = m1 >> 11, sq = m1 & (SEQ - 1);
                    *(uint32_t*)&C[((size_t)((b * NH + h) * SEQ + sq)) * HD + hd] = h1;
                }
                {
                    int b = m2 >> 11, sq = m2 & (SEQ - 1);
                    *(uint32_t*)&C[((size_t)((b * NH + h) * SEQ + sq)) * HD + hd] = h2;
                }
            } else {
                float* C = (float*)Cv;
                float2 r1, r2;
                r1.x = acc[i][j][0] + bb.x;
                r1.y = acc[i][j][1] + bb.y;
                r2.x = acc[i][j][2] + bb.x;
                r2.y = acc[i][j][3] + bb.y;
                *(float2*)&C[(size_t)m1 * DIM + n] = r1;
                *(float2*)&C[(size_t)m2 * DIM + n] = r2;
            }
        }
    }
}

__global__ __launch_bounds__(256, 2) void gemm_qkv(GemmArgs a0, GemmArgs a1, GemmArgs a2) {
    const GemmArgs& a = (blockIdx.z == 0) ? a0 : (blockIdx.z == 1) ? a1 : a2;
    gemm_body<1>(a.A, a.W, a.bias, a.C, a.scale);
}

__global__ __launch_bounds__(256, 2) void gemm_out(const __half* __restrict__ A,
                                                   const __half* __restrict__ W,
                                                   const float* __restrict__ bias,
                                                   float* __restrict__ C) {
    gemm_body<0>(A, W, bias, C, 1.0f);
}

// ---------------------------------------------------------------------------
// fp16 flash attention: Q pre-scaled (S already log2-domain), register-passed
// P, ldmatrix K/V, 3-stage KV ring, per-thread partial l (quad-reduced once),
// mask via per-tile uniform flag. 128 thr (4 warps), 128 q-rows/CTA.
// ---------------------------------------------------------------------------
#define KVROW 144         // bytes per KV row (64 halves + 8 pad)
#define KBUF (FKT * KVROW)        // 9216
#define B_K 0
#define B_V (3 * KBUF)            // 27648
#define FLASH_SMEM_BYTES (6 * KBUF)  // 55296

__global__ __launch_bounds__(128) void flash_attn_tc(__half* __restrict__ Out) {
    extern __shared__ char smem[];
    const uint32_t sbase = smem_u32(smem);

    const int b = blockIdx.z;
    const int h = blockIdx.y;
    const int tid = threadIdx.x;
    const int w = tid >> 5;
    const int lane = tid & 31;
    const int g = lane >> 2;
    const int tig = lane & 3;
    const int jL = lane >> 3;
    const int iL = lane & 7;
    const int qr0 = blockIdx.x * 128 + w * 32;

    const __half* Qp = g_Q + ((size_t)((b * NH + h) * SEQ) + qr0) * HD;
    const __half* Kb = g_K + ((size_t)((b * NH + h) * SEQ)) * HD;
    const __half* Vb = g_V + ((size_t)((b * NH + h) * SEQ)) * HD;

    // Persistent Q A-fragments (pre-scaled by CS)
    uint32_t aQ[2][4][4];
#pragma unroll
    for (int mi = 0; mi < 2; mi++) {
        const __half* Qm = Qp + (size_t)(16 * mi) * HD;
#pragma unroll
        for (int s = 0; s < 4; s++) {
            aQ[mi][s][0] = *(const uint32_t*)&Qm[g * HD + s * 16 + tig * 2];
            aQ[mi][s][1] = *(const uint32_t*)&Qm[(g + 8) * HD + s * 16 + tig * 2];
            aQ[mi][s][2] = *(const uint32_t*)&Qm[g * HD + s * 16 + 8 + tig * 2];
            aQ[mi][s][3] = *(const uint32_t*)&Qm[(g + 8) * HD + s * 16 + 8 + tig * 2];
        }
    }

    float oacc[2][8][4];
#pragma unroll
    for (int mi = 0; mi < 2; mi++)
#pragma unroll
        for (int j = 0; j < 8; j++)
#pragma unroll
            for (int c = 0; c < 4; c++) oacc[mi][j][c] = 0.f;
    float mrun[4] = {-1e30f, -1e30f, -1e30f, -1e30f};
    float lrun[4] = {0.f, 0.f, 0.f, 0.f};   // per-thread PARTIAL sums

    auto stage = [&](int kt, int buf) {
        const __half* Kg = Kb + (size_t)kt * FKT * HD;
        const __half* Vg = Vb + (size_t)kt * FKT * HD;
        const uint32_t dK = sbase + B_K + buf * KBUF;
        const uint32_t dV = sbase + B_V + buf * KBUF;
#pragma unroll
        for (int t = 0; t < 4; t++) {
            int idx = tid + t * 128;       // 0..511
            int row = idx >> 3;            // 0..63
            int c = idx & 7;               // 16B chunk
            CP_ASYNC16(dK + row * KVROW + c * 16, &Kg[row * HD + c * 8]);
            CP_ASYNC16(dV + row * KVROW + c * 16, &Vg[row * HD + c * 8]);
        }
    };

    stage(0, 0);
    CP_ASYNC_COMMIT();
    stage(1, 1);
    CP_ASYNC_COMMIT();

    const int knrow_base = (jL >> 1) * 8 + iL;
    const int kcol = (jL & 1) * 16;
    const int vkrow_base = (jL & 1) * 8 + iL;
    const int vcol = (jL >> 1) * 16;

    int bi = 0, bs = 2;
    for (int kt = 0; kt < FNT; kt++) {
        if (kt < FNT - 1) {
            CP_ASYNC_WAIT(1);
        } else {
            CP_ASYNC_WAIT(0);
        }
        __syncthreads();
        if (kt + 2 < FNT) {
            stage(kt + 2, bs);
            CP_ASYNC_COMMIT();
        }

        const uint32_t Kbuf = sbase + B_K + bi * KBUF;
        const uint32_t Vbuf = sbase + B_V + bi * KBUF;

        // ---- S = Q @ K^T (32 x 64 per warp), 4 k16-steps ----
        float sc[2][8][4];
#pragma unroll
        for (int mi = 0; mi < 2; mi++)
#pragma unroll
            for (int j = 0; j < 8; j++)
#pragma unroll
                for (int c = 0; c < 4; c++) sc[mi][j][c] = 0.f;
#pragma unroll
        for (int s = 0; s < 4; s++) {
            uint32_t bf[8][2];
#pragma unroll
            for (int kg = 0; kg < 4; kg++) {
                uint32_t ad = Kbuf + (16 * kg + knrow_base) * KVROW + s * 32 + kcol;
                LDSM_X4(bf[2 * kg][0], bf[2 * kg][1],
                        bf[2 * kg + 1][0], bf[2 * kg + 1][1], ad);
            }
#pragma unroll
            for (int jn = 0; jn < 8; jn++) {
                MMA_F16(sc[0][jn], aQ[0][s], bf[jn]);
                MMA_F16(sc[1][jn], aQ[1][s], bf[jn]);
            }
        }

        // ---- rare mask path (uniform branch; mask is typically all-zero) ----
        if (g_mflag[b * FNT + kt]) {
            const float* bm = g_bias_m + b * SEQ + kt * FKT;
#pragma unroll
            for (int jn = 0; jn < 8; jn++) {
                float2 bv2 = *(const float2*)&bm[8 * jn + 2 * tig];
#pragma unroll
                for (int mi = 0; mi < 2; mi++) {
                    sc[mi][jn][0] += bv2.x;
                    sc[mi][jn][1] += bv2.y;
                    sc[mi][jn][2] += bv2.x;
                    sc[mi][jn][3] += bv2.y;
                }
            }
        }

        // ---- online softmax (S already in log2 domain) ----
#pragma unroll
        for (int mi = 0; mi < 2; mi++) {
            float mx0 = -1e30f, mx1 = -1e30f;
#pragma unroll
            for (int jn = 0; jn < 8; jn++) {
                mx0 = fmaxf(mx0, fmaxf(sc[mi][jn][0], sc[mi][jn][1]));
                mx1 = fmaxf(mx1, fmaxf(sc[mi][jn][2], sc[mi][jn][3]));
            }
            mx0 = fmaxf(mx0, __shfl_xor_sync(0xFFFFFFFF, mx0, 1));
            mx0 = fmaxf(mx0, __shfl_xor_sync(0xFFFFFFFF, mx0, 2));
            mx1 = fmaxf(mx1, __shfl_xor_sync(0xFFFFFFFF, mx1, 1));
            mx1 = fmaxf(mx1, __shfl_xor_sync(0xFFFFFFFF, mx1, 2));

            const float nm0 = fmaxf(mrun[2 * mi], mx0);
            const float nm1 = fmaxf(mrun[2 * mi + 1], mx1);
            const float cor0 = fast_exp2(mrun[2 * mi] - nm0);
            const float cor1 = fast_exp2(mrun[2 * mi + 1] - nm1);
            mrun[2 * mi] = nm0;
            mrun[2 * mi + 1] = nm1;

            float s0 = 0.f, s1 = 0.f;
#pragma unroll
            for (int jn = 0; jn < 8; jn++) {
                sc[mi][jn][0] = fast_exp2(sc[mi][jn][0] - nm0);
                sc[mi][jn][1] = fast_exp2(sc[mi][jn][1] - nm0);
                sc[mi][jn][2] = fast_exp2(sc[mi][jn][2] - nm1);
                sc[mi][jn][3] = fast_exp2(sc[mi][jn][3] - nm1);
                s0 += sc[mi][jn][0] + sc[mi][jn][1];
                s1 += sc[mi][jn][2] + sc[mi][jn][3];
            }
            // per-thread partial l (corrections are quad-uniform -> exact)
            lrun[2 * mi] = lrun[2 * mi] * cor0 + s0;
            lrun[2 * mi + 1] = lrun[2 * mi + 1] * cor1 + s1;

#pragma unroll
            for (int j = 0; j < 8; j++) {
                oacc[mi][j][0] *= cor0;
                oacc[mi][j][1] *= cor0;
                oacc[mi][j][2] *= cor1;
                oacc[mi][j][3] *= cor1;
            }
        }

        // ---- O += P @ V: P from sc registers, V via ldmatrix.trans ----
#pragma unroll
        for (int s2 = 0; s2 < 4; s2++) {
            uint32_t pa0[4], pa1[4];
            pa0[0] = pack_h2(sc[0][2 * s2][0],     sc[0][2 * s2][1]);
            pa0[1] = pack_h2(sc[0][2 * s2][2],     sc[0][2 * s2][3]);
            pa0[2] = pack_h2(sc[0][2 * s2 + 1][0], sc[0][2 * s2 + 1][1]);
            pa0[3] = pack_h2(sc[0][2 * s2 + 1][2], sc[0][2 * s2 + 1][3]);
            pa1[0] = pack_h2(sc[1][2 * s2][0],     sc[1][2 * s2][1]);
            pa1[1] = pack_h2(sc[1][2 * s2][2],     sc[1][2 * s2][3]);
            pa1[2] = pack_h2(sc[1][2 * s2 + 1][0], sc[1][2 * s2 + 1][1]);
            pa1[3] = pack_h2(sc[1][2 * s2 + 1][2], sc[1][2 * s2 + 1][3]);

            uint32_t bv[8][2];
#pragma unroll
            for (int vg = 0; vg < 4; vg++) {
                uint32_t ad = Vbuf + (16 * s2 + vkrow_base) * KVROW + vg * 32 + vcol;
                LDSM_X4_T(bv[2 * vg][0], bv[2 * vg][1],
                          bv[2 * vg + 1][0], bv[2 * vg + 1][1], ad);
            }
#pragma unroll
            for (int jn2 = 0; jn2 < 8; jn2++) {
                MMA_F16(oacc[0][jn2], pa0, bv[jn2]);
                MMA_F16(oacc[1][jn2], pa1, bv[jn2]);
            }
        }
        bi = (bi == 2) ? 0 : bi + 1;
        bs = (bs == 2) ? 0 : bs + 1;
    }

    // ---- quad-reduce partial l once, then normalize + store ----
#pragma unroll
    for (int i = 0; i < 4; i++) {
        lrun[i] += __shfl_xor_sync(0xFFFFFFFF, lrun[i], 1);
        lrun[i] += __shfl_xor_sync(0xFFFFFFFF, lrun[i], 2);
    }
#pragma unroll
    for (int mi = 0; mi < 2; mi++) {
        const float il0 = 1.f / lrun[2 * mi];
        const float il1 = 1.f / lrun[2 * mi + 1];
        __half* O0 = Out + ((size_t)(b * SEQ + qr0 + 16 * mi + g)) * DIM + h * HD;
        __half* O1 = Out + ((size_t)(b * SEQ + qr0 + 16 * mi + g + 8)) * DIM + h * HD;
#pragma unroll
        for (int jn2 = 0; jn2 < 8; jn2++) {
            *(uint32_t*)&O0[8 * jn2 + 2 * tig] =
                pack_h2(oacc[mi][jn2][0] * il0, oacc[mi][jn2][1] * il0);
            *(uint32_t*)&O1[8 * jn2 + 2 * tig] =
                pack_h2(oacc[mi][jn2][2] * il1, oacc[mi][jn2][3] * il1);
        }
    }
}

// ---------------------------------------------------------------------------
extern "C" void kernel_launch(void* const* d_in, const int* in_sizes, int n_in,
                              void* d_out, int out_size) {
    const float* q  = (const float*)d_in[0];
    const float* k  = (const float*)d_in[1];
    const float* v  = (const float*)d_in[2];
    const int* mask = (const int*)d_in[3];
    const float* Wq = (const float*)d_in[4];
    const float* bq = (const float*)d_in[5];
    const float* Wk = (const float*)d_in[6];
    const float* bk = (const float*)d_in[7];
    const float* Wv = (const float*)d_in[8];
    const float* bv = (const float*)d_in[9];
    const float* Wo = (const float*)d_in[10];
    const float* bo = (const float*)d_in[11];
    float* out = (float*)d_out;

    __half *pQ, *pK, *pV, *pA, *pWh, *pXh;
    float* pBm;
    int* pMf;
    cudaGetSymbolAddress((void**)&pQ, g_Q);
    cudaGetSymbolAddress((void**)&pK, g_K);
    cudaGetSymbolAddress((void**)&pV, g_V);
    cudaGetSymbolAddress((void**)&pA, g_A);
    cudaGetSymbolAddress((void**)&pWh, g_Wh);
    cudaGetSymbolAddress((void**)&pXh, g_Xh);
    cudaGetSymbolAddress((void**)&pBm, g_bias_m);
    cudaGetSymbolAddress((void**)&pMf, g_mflag);

    cudaFuncSetAttribute(gemm_qkv, cudaFuncAttributeMaxDynamicSharedMemorySize, SM_GEMM_TOTAL);
    cudaFuncSetAttribute(gemm_out, cudaFuncAttributeMaxDynamicSharedMemorySize, SM_GEMM_TOTAL);
    cudaFuncSetAttribute(flash_attn_tc, cudaFuncAttributeMaxDynamicSharedMemorySize, FLASH_SMEM_BYTES);

    // --- fused fp32 -> fp16 pre-pass + mask prep ---
    const int W8 = DIM * DIM / 8;       // 131072
    const int X8 = MROWS * DIM / 8;     // 524288
    ConvArgs ca;
    ca.src[0] = Wq; ca.dst[0] = pWh + 0 * (size_t)DIM * DIM; ca.n8[0] = W8;
    ca.src[1] = Wk; ca.dst[1] = pWh + 1 * (size_t)DIM * DIM; ca.n8[1] = W8;
    ca.src[2] = Wv; ca.dst[2] = pWh + 2 * (size_t)DIM * DIM; ca.n8[2] = W8;
    ca.src[3] = Wo; ca.dst[3] = pWh + 3 * (size_t)DIM * DIM; ca.n8[3] = W8;
    ca.src[4] = q;  ca.dst[4] = pXh + 0 * (size_t)MROWS * DIM; ca.n8[4] = X8;
    ca.src[5] = k;  ca.dst[5] = pXh + 1 * (size_t)MROWS * DIM; ca.n8[5] = X8;
    ca.src[6] = v;  ca.dst[6] = pXh + 2 * (size_t)MROWS * DIM; ca.n8[6] = X8;
    ca.mask = mask;
    ca.bias_m = pBm;
    ca.mflag = pMf;
    conv_f16_all<<<dim3(X8 / 1024, 8), 256>>>(ca);

    GemmArgs aq{pXh + 0 * (size_t)MROWS * DIM, pWh + 0 * (size_t)DIM * DIM, bq, pQ, CS};
    GemmArgs ak{pXh + 1 * (size_t)MROWS * DIM, pWh + 1 * (size_t)DIM * DIM, bk, pK, 1.0f};
    GemmArgs av{pXh + 2 * (size_t)MROWS * DIM, pWh + 2 * (size_t)DIM * DIM, bv, pV, 1.0f};

    dim3 gqkv(DIM / GBN, MROWS / GBM, 3);   // (8, 32, 3) = 768 CTAs
    gemm_qkv<<<gqkv, 256, SM_GEMM_TOTAL>>>(aq, ak, av);

    flash_attn_tc<<<dim3(SEQ / 128, NH, BATCH), 128, FLASH_SMEM_BYTES>>>(pA);

    dim3 go(DIM / GBN, MROWS / GBM);        // (8, 32) = 256 CTAs
    gemm_out<<<go, 256, SM_GEMM_TOTAL>>>(pA, pWh + 3 * (size_t)DIM * DIM, bo, out);
}